// round 1
// baseline (speedup 1.0000x reference)
#include <cuda_runtime.h>
#include <math.h>

#define NB     64
#define CH     640
#define HH     28
#define WW     28
#define S1     784
#define S2     196
#define HEADS  8
#define DH     64
#define INNER  512
#define EPS    1e-5f
#define ATT_SCALE 0.125f

// ---- static scratch (no allocations allowed) ----
__device__ float g_dq [NB * CH * S1];        // dwconv+BN (q path)   [b][c][s1]
__device__ float g_dkv[NB * CH * S2];        // dwconv+BN (kv path)  [b][c][s2]
__device__ float g_q  [NB * INNER * S1];     // q projection         [b][co][s1]
__device__ float g_kv [NB * 2 * INNER * S2]; // kv projection        [b][co][s2]
__device__ float g_res[NB * DH * S1];        // residual (pw+BN)     [b][d][s1]

// ---------------------------------------------------------------------------
// Depthwise 3x3 conv + BatchNorm (eval), stride 1 or 2, padding 1.
// ---------------------------------------------------------------------------
__global__ void dwconv_bn_kernel(const float* __restrict__ x,
                                 const float* __restrict__ w,
                                 const float* __restrict__ bg,
                                 const float* __restrict__ bb,
                                 const float* __restrict__ bm,
                                 const float* __restrict__ bv,
                                 float* __restrict__ out,
                                 int stride, int Ho, int Wo, int total)
{
    int idx = blockIdx.x * blockDim.x + threadIdx.x;
    if (idx >= total) return;
    int xo = idx % Wo;
    int t  = idx / Wo;
    int yo = t % Ho; t /= Ho;
    int c  = t % CH;
    int b  = t / CH;

    const float* xp = x + (size_t)(b * CH + c) * S1;
    const float* wp = w + c * 9;

    int yi0 = yo * stride - 1;
    int xi0 = xo * stride - 1;
    float acc = 0.f;
#pragma unroll
    for (int dy = 0; dy < 3; dy++) {
        int yi = yi0 + dy;
        if (yi < 0 || yi >= HH) continue;
#pragma unroll
        for (int dx = 0; dx < 3; dx++) {
            int xi = xi0 + dx;
            if (xi < 0 || xi >= WW) continue;
            acc += xp[yi * WW + xi] * wp[dy * 3 + dx];
        }
    }
    float inv = bg[c] * rsqrtf(bv[c] + EPS);
    out[idx] = (acc - bm[c]) * inv + bb[c];
}

// ---------------------------------------------------------------------------
// Batched SGEMM: C[batch][M][N] = A[M][K] * B[batch][K][N], optional BN on
// output rows (scale/shift per M-row) when bg != nullptr.
// 64x64 tile, 16x16 threads, 4x4 microtile, K-step 16.
// ---------------------------------------------------------------------------
__global__ void gemm_kernel(const float* __restrict__ A,
                            const float* __restrict__ Bmat,
                            float* __restrict__ C,
                            int M, int N, int K,
                            const float* __restrict__ bg,
                            const float* __restrict__ bb,
                            const float* __restrict__ bm,
                            const float* __restrict__ bv)
{
    __shared__ float As[64][17];
    __shared__ float Bs[16][65];

    int batch = blockIdx.z;
    const float* Bb = Bmat + (size_t)batch * K * N;
    float*       Cb = C    + (size_t)batch * M * N;

    int tx = threadIdx.x & 15;
    int ty = threadIdx.x >> 4;
    int row0 = blockIdx.y * 64;
    int col0 = blockIdx.x * 64;

    float acc[4][4];
#pragma unroll
    for (int i = 0; i < 4; i++)
#pragma unroll
        for (int j = 0; j < 4; j++) acc[i][j] = 0.f;

    for (int k0 = 0; k0 < K; k0 += 16) {
#pragma unroll
        for (int l = 0; l < 4; l++) {
            int i  = threadIdx.x + l * 256;
            int r  = i >> 4, kk = i & 15;
            int gr = row0 + r;
            As[r][kk] = (gr < M) ? A[(size_t)gr * K + k0 + kk] : 0.f;
        }
#pragma unroll
        for (int l = 0; l < 4; l++) {
            int i  = threadIdx.x + l * 256;
            int kk = i >> 6, c = i & 63;
            int gc = col0 + c;
            Bs[kk][c] = (gc < N) ? Bb[(size_t)(k0 + kk) * N + gc] : 0.f;
        }
        __syncthreads();
#pragma unroll
        for (int kk = 0; kk < 16; kk++) {
            float av[4], bw[4];
#pragma unroll
            for (int i = 0; i < 4; i++) av[i] = As[ty * 4 + i][kk];
#pragma unroll
            for (int j = 0; j < 4; j++) bw[j] = Bs[kk][tx * 4 + j];
#pragma unroll
            for (int i = 0; i < 4; i++)
#pragma unroll
                for (int j = 0; j < 4; j++)
                    acc[i][j] += av[i] * bw[j];
        }
        __syncthreads();
    }

#pragma unroll
    for (int i = 0; i < 4; i++) {
        int r = row0 + ty * 4 + i;
        if (r >= M) continue;
        float sc = 1.f, sh = 0.f;
        if (bg) {
            float inv = bg[r] * rsqrtf(bv[r] + EPS);
            sc = inv;
            sh = bb[r] - bm[r] * inv;
        }
#pragma unroll
        for (int j = 0; j < 4; j++) {
            int c = col0 + tx * 4 + j;
            if (c < N) Cb[(size_t)r * N + c] = acc[i][j] * sc + sh;
        }
    }
}

// ---------------------------------------------------------------------------
// Fused attention + residual + per-head LayerNorm + spatial mean.
// One block per (b, h): K/V [196][64] staged once in SMEM (padded 65);
// Q and residual staged in 64-column tiles (coalesced); each warp owns one
// q-row at a time (full softmax over 196 keys in registers/SMEM); LN over the
// 64-channel row (x = attn_out + residual); result accumulated per-block and
// divided by 784 at the end.
// ---------------------------------------------------------------------------
__global__ void attn_kernel(const float* __restrict__ qb,
                            const float* __restrict__ kvb,
                            const float* __restrict__ resb,
                            const float* __restrict__ lng,
                            const float* __restrict__ lnb,
                            float* __restrict__ out)
{
    extern __shared__ float sm[];
    float* Ks   = sm;                 // [196][65]
    float* Vs   = Ks + S2 * 65;       // [196][65]
    float* Qs   = Vs + S2 * 65;       // [64][65]
    float* Rs   = Qs + 64 * 65;       // [64][65]
    float* Ps   = Rs + 64 * 65;       // [8][208]
    float* accs = Ps + 8 * 208;       // [8][64]

    int bh   = blockIdx.x;
    int b    = bh >> 3, h = bh & 7;
    int tid  = threadIdx.x;
    int w    = tid >> 5, lane = tid & 31;

    // stage K,V transposed: Ks[s2][d] <- kv[b][h*64+d][s2]
    const float* kbase = kvb + ((size_t)b * (2 * INNER) + h * DH) * S2;
    const float* vbase = kbase + (size_t)INNER * S2;
    for (int i = tid; i < S2 * DH; i += 256) {
        int d = i / S2, s2 = i - d * S2;
        Ks[s2 * 65 + d] = kbase[(size_t)d * S2 + s2];
        Vs[s2 * 65 + d] = vbase[(size_t)d * S2 + s2];
    }
    for (int i = tid; i < 8 * 64; i += 256) accs[i] = 0.f;

    float lg0 = lng[h * DH + lane], lg1 = lng[h * DH + lane + 32];
    float lb0 = lnb[h * DH + lane], lb1 = lnb[h * DH + lane + 32];

    const float* qbase = qb   + ((size_t)b * INNER + h * DH) * S1;
    const float* rbase = resb + (size_t)b * DH * S1;

    int koff[7];
#pragma unroll
    for (int t = 0; t < 7; t++) {
        int j = lane + 32 * t;
        koff[t] = ((j < S2) ? j : 0) * 65;
    }
    bool v6 = (lane < 4);  // j = 192+lane valid only for lane<4 (196 keys)

    for (int s0 = 0; s0 < S1; s0 += 64) {
        int len = min(64, S1 - s0);
        __syncthreads();  // previous readers of Qs/Rs done (also covers K/V/acc init)
        for (int i = tid; i < 64 * 64; i += 256) {
            int d = i >> 6, sc = i & 63;
            if (sc < len) {
                Qs[sc * 65 + d] = qbase[(size_t)d * S1 + s0 + sc];
                Rs[sc * 65 + d] = rbase[(size_t)d * S1 + s0 + sc];
            }
        }
        __syncthreads();

        for (int r = w; r < len; r += 8) {
            const float* qrow = &Qs[r * 65];
            float dots[7];
#pragma unroll
            for (int t = 0; t < 7; t++) dots[t] = 0.f;
            for (int d = 0; d < DH; d++) {
                float qd = qrow[d];
#pragma unroll
                for (int t = 0; t < 7; t++)
                    dots[t] += qd * Ks[koff[t] + d];
            }
#pragma unroll
            for (int t = 0; t < 7; t++) dots[t] *= ATT_SCALE;

            float mx = dots[0];
#pragma unroll
            for (int t = 1; t < 6; t++) mx = fmaxf(mx, dots[t]);
            if (v6) mx = fmaxf(mx, dots[6]);
#pragma unroll
            for (int o = 16; o > 0; o >>= 1)
                mx = fmaxf(mx, __shfl_xor_sync(0xffffffffu, mx, o));

            float p[7], Z = 0.f;
#pragma unroll
            for (int t = 0; t < 6; t++) { p[t] = __expf(dots[t] - mx); Z += p[t]; }
            p[6] = v6 ? __expf(dots[6] - mx) : 0.f;
            Z += p[6];
#pragma unroll
            for (int o = 16; o > 0; o >>= 1)
                Z += __shfl_xor_sync(0xffffffffu, Z, o);

            float* Prow = &Ps[w * 208];
#pragma unroll
            for (int t = 0; t < 6; t++) Prow[lane + 32 * t] = p[t];
            if (v6) Prow[lane + 192] = p[6];
            __syncwarp();

            float o0 = 0.f, o1 = 0.f;
            for (int j = 0; j < S2; j++) {
                float pj = Prow[j];
                o0 += pj * Vs[j * 65 + lane];
                o1 += pj * Vs[j * 65 + lane + 32];
            }
            float rZ = 1.f / Z;
            float x0 = o0 * rZ + Rs[r * 65 + lane];
            float x1 = o1 * rZ + Rs[r * 65 + lane + 32];

            // per-row LayerNorm over d=64 (biased var; eps added to std)
            float sum = x0 + x1, sq = x0 * x0 + x1 * x1;
#pragma unroll
            for (int o = 16; o > 0; o >>= 1) {
                sum += __shfl_xor_sync(0xffffffffu, sum, o);
                sq  += __shfl_xor_sync(0xffffffffu, sq,  o);
            }
            float mean = sum * (1.f / 64.f);
            float var  = fmaxf(sq * (1.f / 64.f) - mean * mean, 0.f);
            float rs   = 1.f / (sqrtf(var) + EPS);
            accs[w * 64 + lane]      += (x0 - mean) * rs * lg0 + lb0;
            accs[w * 64 + lane + 32] += (x1 - mean) * rs * lg1 + lb1;
            __syncwarp();  // WAR on Prow before next row's writes
        }
    }

    __syncthreads();
    if (tid < 64) {
        float s = 0.f;
#pragma unroll
        for (int w2 = 0; w2 < 8; w2++) s += accs[w2 * 64 + tid];
        out[((size_t)b * HEADS + h) * DH + tid] = s * (1.f / 784.f);
    }
}

// ---------------------------------------------------------------------------
extern "C" void kernel_launch(void* const* d_in, const int* in_sizes, int n_in,
                              void* d_out, int out_size)
{
    const float* x      = (const float*)d_in[0];
    const float* w_dwq  = (const float*)d_in[1];
    const float* w_pwq  = (const float*)d_in[2];
    const float* w_dwkv = (const float*)d_in[3];
    const float* w_pwkv = (const float*)d_in[4];
    const float* w_ds   = (const float*)d_in[5];
    const float* ln_g   = (const float*)d_in[6];
    const float* ln_b   = (const float*)d_in[7];
    const float* bnq_g  = (const float*)d_in[8];
    const float* bnq_b  = (const float*)d_in[9];
    const float* bnq_m  = (const float*)d_in[10];
    const float* bnq_v  = (const float*)d_in[11];
    const float* bnkv_g = (const float*)d_in[12];
    const float* bnkv_b = (const float*)d_in[13];
    const float* bnkv_m = (const float*)d_in[14];
    const float* bnkv_v = (const float*)d_in[15];
    const float* bnds_g = (const float*)d_in[16];
    const float* bnds_b = (const float*)d_in[17];
    const float* bnds_m = (const float*)d_in[18];
    const float* bnds_v = (const float*)d_in[19];
    float* out = (float*)d_out;

    void *p_dq, *p_dkv, *p_q, *p_kv, *p_res;
    cudaGetSymbolAddress(&p_dq,  g_dq);
    cudaGetSymbolAddress(&p_dkv, g_dkv);
    cudaGetSymbolAddress(&p_q,   g_q);
    cudaGetSymbolAddress(&p_kv,  g_kv);
    cudaGetSymbolAddress(&p_res, g_res);

    // 1) depthwise convs + BN
    {
        int total = NB * CH * S1;
        dwconv_bn_kernel<<<(total + 255) / 256, 256>>>(
            x, w_dwq, bnq_g, bnq_b, bnq_m, bnq_v,
            (float*)p_dq, 1, HH, WW, total);
    }
    {
        int total = NB * CH * S2;
        dwconv_bn_kernel<<<(total + 255) / 256, 256>>>(
            x, w_dwkv, bnkv_g, bnkv_b, bnkv_m, bnkv_v,
            (float*)p_dkv, 2, 14, 14, total);
    }

    // 2) pointwise projections as batched GEMMs
    {
        dim3 grid((S1 + 63) / 64, 1, NB);  // residual: M=64,N=784,K=640 (+BN)
        gemm_kernel<<<grid, 256>>>(w_ds, x, (float*)p_res, DH, S1, CH,
                                   bnds_g, bnds_b, bnds_m, bnds_v);
    }
    {
        dim3 grid((S1 + 63) / 64, INNER / 64, NB);  // q: M=512,N=784,K=640
        gemm_kernel<<<grid, 256>>>(w_pwq, (const float*)p_dq, (float*)p_q,
                                   INNER, S1, CH, nullptr, nullptr, nullptr, nullptr);
    }
    {
        dim3 grid((S2 + 63) / 64, (2 * INNER) / 64, NB);  // kv: M=1024,N=196,K=640
        gemm_kernel<<<grid, 256>>>(w_pwkv, (const float*)p_dkv, (float*)p_kv,
                                   2 * INNER, S2, CH, nullptr, nullptr, nullptr, nullptr);
    }

    // 3) fused attention + residual + LN + spatial mean
    {
        size_t smem = (size_t)(S2 * 65 * 2 + 64 * 65 * 2 + 8 * 208 + 8 * 64) * sizeof(float);
        cudaFuncSetAttribute(attn_kernel, cudaFuncAttributeMaxDynamicSharedMemorySize,
                             (int)smem);
        attn_kernel<<<NB * HEADS, 256, smem>>>(
            (const float*)p_q, (const float*)p_kv, (const float*)p_res,
            ln_g, ln_b, out);
    }
}

// round 2
// speedup vs baseline: 1.5477x; 1.5477x over previous
#include <cuda_runtime.h>
#include <math.h>

#define NB     64
#define CH     640
#define HH     28
#define WW     28
#define S1     784
#define S2     196
#define HEADS  8
#define DH     64
#define INNER  512
#define EPS    1e-5f
#define ATT_SCALE 0.125f

// ---- static scratch (no allocations allowed) ----
__device__ float g_dq [NB * CH * S1];        // dwconv+BN (q path), tf32-rounded
__device__ float g_dkv[NB * CH * S2];        // dwconv+BN (kv path), tf32-rounded
__device__ float g_q  [NB * INNER * S1];     // q projection
__device__ float g_kv [NB * 2 * INNER * S2]; // kv projection
__device__ float g_res[NB * DH * S1];        // residual (pw+BN)
__device__ float g_xr [NB * CH * S1];        // x, tf32-rounded (residual GEMM B)
__device__ float g_wq [INNER * CH];          // tf32-rounded weights
__device__ float g_wkv[2 * INNER * CH];
__device__ float g_wds[DH * CH];

// ---------------------------------------------------------------------------
__device__ __forceinline__ float tf32r(float x) {
    unsigned int u;
    asm("cvt.rna.tf32.f32 %0, %1;" : "=r"(u) : "f"(x));
    return __uint_as_float(u);
}

__global__ void round_tf32_kernel(const float* __restrict__ in,
                                  float* __restrict__ out, int n4)
{
    int i = blockIdx.x * blockDim.x + threadIdx.x;
    if (i >= n4) return;
    float4 v = ((const float4*)in)[i];
    v.x = tf32r(v.x); v.y = tf32r(v.y); v.z = tf32r(v.z); v.w = tf32r(v.w);
    ((float4*)out)[i] = v;
}

// ---------------------------------------------------------------------------
// Depthwise 3x3 conv + BatchNorm (eval), stride 1 or 2, padding 1.
// Output rounded to tf32 (feeds tensor-core GEMM).
// ---------------------------------------------------------------------------
__global__ void dwconv_bn_kernel(const float* __restrict__ x,
                                 const float* __restrict__ w,
                                 const float* __restrict__ bg,
                                 const float* __restrict__ bb,
                                 const float* __restrict__ bm,
                                 const float* __restrict__ bv,
                                 float* __restrict__ out,
                                 int stride, int Ho, int Wo, int total)
{
    int idx = blockIdx.x * blockDim.x + threadIdx.x;
    if (idx >= total) return;
    int xo = idx % Wo;
    int t  = idx / Wo;
    int yo = t % Ho; t /= Ho;
    int c  = t % CH;
    int b  = t / CH;

    const float* xp = x + (size_t)(b * CH + c) * S1;
    const float* wp = w + c * 9;

    int yi0 = yo * stride - 1;
    int xi0 = xo * stride - 1;
    float acc = 0.f;
#pragma unroll
    for (int dy = 0; dy < 3; dy++) {
        int yi = yi0 + dy;
        if (yi < 0 || yi >= HH) continue;
#pragma unroll
        for (int dx = 0; dx < 3; dx++) {
            int xi = xi0 + dx;
            if (xi < 0 || xi >= WW) continue;
            acc += xp[yi * WW + xi] * wp[dy * 3 + dx];
        }
    }
    float inv = bg[c] * rsqrtf(bv[c] + EPS);
    out[idx] = tf32r((acc - bm[c]) * inv + bb[c]);
}

// ---------------------------------------------------------------------------
// Tensor-core batched GEMM (tf32 mma.sync.m16n8k8):
//   C[z][M][N] = A[M][K] * B[z][K][N], A shared across batch.
// Block tile 128x128, 8 warps (warp tile 64x32), k-step 16, double-buffered.
// Optional per-row BN epilogue when bg != nullptr.
// Operands must be pre-rounded to tf32-representable fp32.
// ---------------------------------------------------------------------------
#define PA 20
#define PB 136

__device__ __forceinline__ void mma_tf32(float* c, const unsigned int* a,
                                         const unsigned int* b)
{
    asm volatile(
        "mma.sync.aligned.m16n8k8.row.col.f32.tf32.tf32.f32 "
        "{%0,%1,%2,%3}, {%4,%5,%6,%7}, {%8,%9}, {%0,%1,%2,%3};\n"
        : "+f"(c[0]), "+f"(c[1]), "+f"(c[2]), "+f"(c[3])
        : "r"(a[0]), "r"(a[1]), "r"(a[2]), "r"(a[3]), "r"(b[0]), "r"(b[1]));
}

__global__ void __launch_bounds__(256, 2)
gemm_tc_kernel(const float* __restrict__ A,
               const float* __restrict__ Bmat,
               float* __restrict__ C,
               int M, int N, int K,
               const float* __restrict__ bg,
               const float* __restrict__ bb,
               const float* __restrict__ bm,
               const float* __restrict__ bv)
{
    __shared__ __align__(16) float As[2][128 * PA];
    __shared__ __align__(16) float Bs[2][16 * PB];

    const int tid  = threadIdx.x;
    const int lane = tid & 31;
    const int wid  = tid >> 5;
    const int wm   = (wid >> 2) * 64;   // warp M offset in block tile
    const int wn   = (wid & 3) * 32;    // warp N offset
    const int g    = lane >> 2;         // group id 0..7
    const int t    = lane & 3;          // thread-in-group 0..3

    const int row0  = blockIdx.y * 128;
    const int col0  = blockIdx.x * 128;
    const int batch = blockIdx.z;
    const float* Bb = Bmat + (size_t)batch * K * N;
    float*       Cb = C    + (size_t)batch * M * N;

    // load indices (two float4 each for A and B per thread per k-step)
    const int am0 = tid >> 2;            // rows tid/4 and tid/4+64
    const int af4 = (tid & 3) * 4;       // k offset within 16
    const int bk0 = tid >> 5;            // k rows tid/32 and tid/32+8
    const int bn  = (tid & 31) * 4;      // n offset within 128
    const bool bok = (col0 + bn) < N;    // N % 4 == 0 -> whole float4 valid or not

    float c[4][4][4];
#pragma unroll
    for (int i = 0; i < 4; i++)
#pragma unroll
        for (int j = 0; j < 4; j++)
#pragma unroll
            for (int l = 0; l < 4; l++) c[i][j][l] = 0.f;

    const int NKT = K / 16;  // 40

    // prologue: fill buffer 0
    {
        float4 ra0 = make_float4(0, 0, 0, 0), ra1 = ra0, rb0 = ra0, rb1 = ra0;
        if (row0 + am0      < M) ra0 = *(const float4*)&A[(size_t)(row0 + am0)      * K + af4];
        if (row0 + am0 + 64 < M) ra1 = *(const float4*)&A[(size_t)(row0 + am0 + 64) * K + af4];
        if (bok) {
            rb0 = *(const float4*)&Bb[(size_t)(bk0    ) * N + col0 + bn];
            rb1 = *(const float4*)&Bb[(size_t)(bk0 + 8) * N + col0 + bn];
        }
        *(float4*)&As[0][(am0)      * PA + af4] = ra0;
        *(float4*)&As[0][(am0 + 64) * PA + af4] = ra1;
        *(float4*)&Bs[0][(bk0)      * PB + bn]  = rb0;
        *(float4*)&Bs[0][(bk0 + 8)  * PB + bn]  = rb1;
    }
    __syncthreads();

    for (int kt = 0; kt < NKT; kt++) {
        const int cur = kt & 1;
        float4 ra0, ra1, rb0, rb1;
        const bool has_next = (kt + 1) < NKT;
        if (has_next) {
            const int k0 = (kt + 1) * 16;
            ra0 = make_float4(0, 0, 0, 0); ra1 = ra0; rb0 = ra0; rb1 = ra0;
            if (row0 + am0      < M) ra0 = *(const float4*)&A[(size_t)(row0 + am0)      * K + k0 + af4];
            if (row0 + am0 + 64 < M) ra1 = *(const float4*)&A[(size_t)(row0 + am0 + 64) * K + k0 + af4];
            if (bok) {
                rb0 = *(const float4*)&Bb[(size_t)(k0 + bk0    ) * N + col0 + bn];
                rb1 = *(const float4*)&Bb[(size_t)(k0 + bk0 + 8) * N + col0 + bn];
            }
        }

        const unsigned int* Asu = (const unsigned int*)&As[cur][0];
        const unsigned int* Bsu = (const unsigned int*)&Bs[cur][0];
#pragma unroll
        for (int ks = 0; ks < 2; ks++) {
            unsigned int af[4][4], bf[4][2];
#pragma unroll
            for (int mt = 0; mt < 4; mt++) {
                int mb = wm + mt * 16;
                af[mt][0] = Asu[(mb + g    ) * PA + ks * 8 + t];
                af[mt][1] = Asu[(mb + g + 8) * PA + ks * 8 + t];
                af[mt][2] = Asu[(mb + g    ) * PA + ks * 8 + t + 4];
                af[mt][3] = Asu[(mb + g + 8) * PA + ks * 8 + t + 4];
            }
#pragma unroll
            for (int nt = 0; nt < 4; nt++) {
                int nb = wn + nt * 8 + g;
                bf[nt][0] = Bsu[(ks * 8 + t    ) * PB + nb];
                bf[nt][1] = Bsu[(ks * 8 + t + 4) * PB + nb];
            }
#pragma unroll
            for (int mt = 0; mt < 4; mt++)
#pragma unroll
                for (int nt = 0; nt < 4; nt++)
                    mma_tf32(c[mt][nt], af[mt], bf[nt]);
        }

        if (has_next) {
            const int nxt = cur ^ 1;
            *(float4*)&As[nxt][(am0)      * PA + af4] = ra0;
            *(float4*)&As[nxt][(am0 + 64) * PA + af4] = ra1;
            *(float4*)&Bs[nxt][(bk0)      * PB + bn]  = rb0;
            *(float4*)&Bs[nxt][(bk0 + 8)  * PB + bn]  = rb1;
        }
        __syncthreads();
    }

    // epilogue
#pragma unroll
    for (int mt = 0; mt < 4; mt++) {
        int r0 = row0 + wm + mt * 16 + g;
        int r1 = r0 + 8;
        float sc0 = 1.f, sh0 = 0.f, sc1 = 1.f, sh1 = 0.f;
        if (bg) {
            if (r0 < M) {
                float inv = bg[r0] * rsqrtf(bv[r0] + EPS);
                sc0 = inv; sh0 = bb[r0] - bm[r0] * inv;
            }
            if (r1 < M) {
                float inv = bg[r1] * rsqrtf(bv[r1] + EPS);
                sc1 = inv; sh1 = bb[r1] - bm[r1] * inv;
            }
        }
#pragma unroll
        for (int nt = 0; nt < 4; nt++) {
            int cc = col0 + wn + nt * 8 + 2 * t;
            if (cc < N) {  // N even -> cc+1 valid too
                if (r0 < M) {
                    float2 v = make_float2(c[mt][nt][0] * sc0 + sh0,
                                           c[mt][nt][1] * sc0 + sh0);
                    *(float2*)&Cb[(size_t)r0 * N + cc] = v;
                }
                if (r1 < M) {
                    float2 v = make_float2(c[mt][nt][2] * sc1 + sh1,
                                           c[mt][nt][3] * sc1 + sh1);
                    *(float2*)&Cb[(size_t)r1 * N + cc] = v;
                }
            }
        }
    }
}

// ---------------------------------------------------------------------------
// Fused attention + residual + per-head LayerNorm + spatial mean.
// (unchanged from Round 1 — correct, ~0.5 ms; next optimization target)
// ---------------------------------------------------------------------------
__global__ void attn_kernel(const float* __restrict__ qb,
                            const float* __restrict__ kvb,
                            const float* __restrict__ resb,
                            const float* __restrict__ lng,
                            const float* __restrict__ lnb,
                            float* __restrict__ out)
{
    extern __shared__ float sm[];
    float* Ks   = sm;                 // [196][65]
    float* Vs   = Ks + S2 * 65;       // [196][65]
    float* Qs   = Vs + S2 * 65;       // [64][65]
    float* Rs   = Qs + 64 * 65;       // [64][65]
    float* Ps   = Rs + 64 * 65;       // [8][208]
    float* accs = Ps + 8 * 208;       // [8][64]

    int bh   = blockIdx.x;
    int b    = bh >> 3, h = bh & 7;
    int tid  = threadIdx.x;
    int w    = tid >> 5, lane = tid & 31;

    const float* kbase = kvb + ((size_t)b * (2 * INNER) + h * DH) * S2;
    const float* vbase = kbase + (size_t)INNER * S2;
    for (int i = tid; i < S2 * DH; i += 256) {
        int d = i / S2, s2 = i - d * S2;
        Ks[s2 * 65 + d] = kbase[(size_t)d * S2 + s2];
        Vs[s2 * 65 + d] = vbase[(size_t)d * S2 + s2];
    }
    for (int i = tid; i < 8 * 64; i += 256) accs[i] = 0.f;

    float lg0 = lng[h * DH + lane], lg1 = lng[h * DH + lane + 32];
    float lb0 = lnb[h * DH + lane], lb1 = lnb[h * DH + lane + 32];

    const float* qbase = qb   + ((size_t)b * INNER + h * DH) * S1;
    const float* rbase = resb + (size_t)b * DH * S1;

    int koff[7];
#pragma unroll
    for (int t = 0; t < 7; t++) {
        int j = lane + 32 * t;
        koff[t] = ((j < S2) ? j : 0) * 65;
    }
    bool v6 = (lane < 4);

    for (int s0 = 0; s0 < S1; s0 += 64) {
        int len = min(64, S1 - s0);
        __syncthreads();
        for (int i = tid; i < 64 * 64; i += 256) {
            int d = i >> 6, sc = i & 63;
            if (sc < len) {
                Qs[sc * 65 + d] = qbase[(size_t)d * S1 + s0 + sc];
                Rs[sc * 65 + d] = rbase[(size_t)d * S1 + s0 + sc];
            }
        }
        __syncthreads();

        for (int r = w; r < len; r += 8) {
            const float* qrow = &Qs[r * 65];
            float dots[7];
#pragma unroll
            for (int t = 0; t < 7; t++) dots[t] = 0.f;
            for (int d = 0; d < DH; d++) {
                float qd = qrow[d];
#pragma unroll
                for (int t = 0; t < 7; t++)
                    dots[t] += qd * Ks[koff[t] + d];
            }
#pragma unroll
            for (int t = 0; t < 7; t++) dots[t] *= ATT_SCALE;

            float mx = dots[0];
#pragma unroll
            for (int t = 1; t < 6; t++) mx = fmaxf(mx, dots[t]);
            if (v6) mx = fmaxf(mx, dots[6]);
#pragma unroll
            for (int o = 16; o > 0; o >>= 1)
                mx = fmaxf(mx, __shfl_xor_sync(0xffffffffu, mx, o));

            float p[7], Z = 0.f;
#pragma unroll
            for (int t = 0; t < 6; t++) { p[t] = __expf(dots[t] - mx); Z += p[t]; }
            p[6] = v6 ? __expf(dots[6] - mx) : 0.f;
            Z += p[6];
#pragma unroll
            for (int o = 16; o > 0; o >>= 1)
                Z += __shfl_xor_sync(0xffffffffu, Z, o);

            float* Prow = &Ps[w * 208];
#pragma unroll
            for (int t = 0; t < 6; t++) Prow[lane + 32 * t] = p[t];
            if (v6) Prow[lane + 192] = p[6];
            __syncwarp();

            float o0 = 0.f, o1 = 0.f;
            for (int j = 0; j < S2; j++) {
                float pj = Prow[j];
                o0 += pj * Vs[j * 65 + lane];
                o1 += pj * Vs[j * 65 + lane + 32];
            }
            float rZ = 1.f / Z;
            float x0 = o0 * rZ + Rs[r * 65 + lane];
            float x1 = o1 * rZ + Rs[r * 65 + lane + 32];

            float sum = x0 + x1, sq = x0 * x0 + x1 * x1;
#pragma unroll
            for (int o = 16; o > 0; o >>= 1) {
                sum += __shfl_xor_sync(0xffffffffu, sum, o);
                sq  += __shfl_xor_sync(0xffffffffu, sq,  o);
            }
            float mean = sum * (1.f / 64.f);
            float var  = fmaxf(sq * (1.f / 64.f) - mean * mean, 0.f);
            float rs   = 1.f / (sqrtf(var) + EPS);
            accs[w * 64 + lane]      += (x0 - mean) * rs * lg0 + lb0;
            accs[w * 64 + lane + 32] += (x1 - mean) * rs * lg1 + lb1;
            __syncwarp();
        }
    }

    __syncthreads();
    if (tid < 64) {
        float s = 0.f;
#pragma unroll
        for (int w2 = 0; w2 < 8; w2++) s += accs[w2 * 64 + tid];
        out[((size_t)b * HEADS + h) * DH + tid] = s * (1.f / 784.f);
    }
}

// ---------------------------------------------------------------------------
extern "C" void kernel_launch(void* const* d_in, const int* in_sizes, int n_in,
                              void* d_out, int out_size)
{
    const float* x      = (const float*)d_in[0];
    const float* w_dwq  = (const float*)d_in[1];
    const float* w_pwq  = (const float*)d_in[2];
    const float* w_dwkv = (const float*)d_in[3];
    const float* w_pwkv = (const float*)d_in[4];
    const float* w_ds   = (const float*)d_in[5];
    const float* ln_g   = (const float*)d_in[6];
    const float* ln_b   = (const float*)d_in[7];
    const float* bnq_g  = (const float*)d_in[8];
    const float* bnq_b  = (const float*)d_in[9];
    const float* bnq_m  = (const float*)d_in[10];
    const float* bnq_v  = (const float*)d_in[11];
    const float* bnkv_g = (const float*)d_in[12];
    const float* bnkv_b = (const float*)d_in[13];
    const float* bnkv_m = (const float*)d_in[14];
    const float* bnkv_v = (const float*)d_in[15];
    const float* bnds_g = (const float*)d_in[16];
    const float* bnds_b = (const float*)d_in[17];
    const float* bnds_m = (const float*)d_in[18];
    const float* bnds_v = (const float*)d_in[19];
    float* out = (float*)d_out;

    void *p_dq, *p_dkv, *p_q, *p_kv, *p_res, *p_xr, *p_wq, *p_wkv, *p_wds;
    cudaGetSymbolAddress(&p_dq,  g_dq);
    cudaGetSymbolAddress(&p_dkv, g_dkv);
    cudaGetSymbolAddress(&p_q,   g_q);
    cudaGetSymbolAddress(&p_kv,  g_kv);
    cudaGetSymbolAddress(&p_res, g_res);
    cudaGetSymbolAddress(&p_xr,  g_xr);
    cudaGetSymbolAddress(&p_wq,  g_wq);
    cudaGetSymbolAddress(&p_wkv, g_wkv);
    cudaGetSymbolAddress(&p_wds, g_wds);

    // 0) tf32 pre-rounding of GEMM operands (memory-bound elementwise)
    {
        int n4 = NB * CH * S1 / 4;
        round_tf32_kernel<<<(n4 + 255) / 256, 256>>>(x, (float*)p_xr, n4);
    }
    {
        int n4 = INNER * CH / 4;
        round_tf32_kernel<<<(n4 + 255) / 256, 256>>>(w_pwq, (float*)p_wq, n4);
    }
    {
        int n4 = 2 * INNER * CH / 4;
        round_tf32_kernel<<<(n4 + 255) / 256, 256>>>(w_pwkv, (float*)p_wkv, n4);
    }
    {
        int n4 = DH * CH / 4;
        round_tf32_kernel<<<(n4 + 255) / 256, 256>>>(w_ds, (float*)p_wds, n4);
    }

    // 1) depthwise convs + BN (outputs tf32-rounded)
    {
        int total = NB * CH * S1;
        dwconv_bn_kernel<<<(total + 255) / 256, 256>>>(
            x, w_dwq, bnq_g, bnq_b, bnq_m, bnq_v,
            (float*)p_dq, 1, HH, WW, total);
    }
    {
        int total = NB * CH * S2;
        dwconv_bn_kernel<<<(total + 255) / 256, 256>>>(
            x, w_dwkv, bnkv_g, bnkv_b, bnkv_m, bnkv_v,
            (float*)p_dkv, 2, 14, 14, total);
    }

    // 2) pointwise projections as tensor-core batched GEMMs
    {
        dim3 grid((S1 + 127) / 128, 1, NB);  // residual: M=64,N=784,K=640 (+BN)
        gemm_tc_kernel<<<grid, 256>>>((const float*)p_wds, (const float*)p_xr,
                                      (float*)p_res, DH, S1, CH,
                                      bnds_g, bnds_b, bnds_m, bnds_v);
    }
    {
        dim3 grid((S1 + 127) / 128, INNER / 128, NB);  // q: M=512,N=784,K=640
        gemm_tc_kernel<<<grid, 256>>>((const float*)p_wq, (const float*)p_dq,
                                      (float*)p_q, INNER, S1, CH,
                                      nullptr, nullptr, nullptr, nullptr);
    }
    {
        dim3 grid((S2 + 127) / 128, (2 * INNER) / 128, NB);  // kv: M=1024,N=196,K=640
        gemm_tc_kernel<<<grid, 256>>>((const float*)p_wkv, (const float*)p_dkv,
                                      (float*)p_kv, 2 * INNER, S2, CH,
                                      nullptr, nullptr, nullptr, nullptr);
    }

    // 3) fused attention + residual + LN + spatial mean
    {
        size_t smem = (size_t)(S2 * 65 * 2 + 64 * 65 * 2 + 8 * 208 + 8 * 64) * sizeof(float);
        cudaFuncSetAttribute(attn_kernel, cudaFuncAttributeMaxDynamicSharedMemorySize,
                             (int)smem);
        attn_kernel<<<NB * HEADS, 256, smem>>>(
            (const float*)p_q, (const float*)p_kv, (const float*)p_res,
            ln_g, ln_b, out);
    }
}

// round 3
// speedup vs baseline: 2.7320x; 1.7651x over previous
#include <cuda_runtime.h>
#include <math.h>

#define NB     64
#define CH     640
#define HH     28
#define WW     28
#define S1     784
#define S2     196
#define HEADS  8
#define DH     64
#define INNER  512
#define EPS    1e-5f
#define ATT_SCALE 0.125f

// attention tiling constants
#define NPAD   208            // padded key count for QK n-dim (13 mma tiles of 8)
#define KSTR   232            // Ksm row stride (≡8 mod 32 -> conflict-free B-frags)
#define VROWS  200            // padded V rows (25 k-steps of 8)
#define VSTR   72             // Vsm row stride (≡8 mod 32)
#define QSTR   68             // Qsm/Osm row stride (A-frag conflict-free)
#define SSTR   212            // Ssm row stride (A-frag conflict-free: 212%32=20)

// ---- static scratch (no allocations allowed) ----
__device__ float g_dq [NB * CH * S1];
__device__ float g_dkv[NB * CH * S2];
__device__ float g_q  [NB * INNER * S1];
__device__ float g_kv [NB * 2 * INNER * S2];
__device__ float g_res[NB * DH * S1];
__device__ float g_xr [NB * CH * S1];
__device__ float g_wq [INNER * CH];
__device__ float g_wkv[2 * INNER * CH];
__device__ float g_wds[DH * CH];

// ---------------------------------------------------------------------------
__device__ __forceinline__ float tf32r(float x) {
    unsigned int u;
    asm("cvt.rna.tf32.f32 %0, %1;" : "=r"(u) : "f"(x));
    return __uint_as_float(u);
}

__global__ void round_tf32_kernel(const float* __restrict__ in,
                                  float* __restrict__ out, int n4)
{
    int i = blockIdx.x * blockDim.x + threadIdx.x;
    if (i >= n4) return;
    float4 v = ((const float4*)in)[i];
    v.x = tf32r(v.x); v.y = tf32r(v.y); v.z = tf32r(v.z); v.w = tf32r(v.w);
    ((float4*)out)[i] = v;
}

// ---------------------------------------------------------------------------
__global__ void dwconv_bn_kernel(const float* __restrict__ x,
                                 const float* __restrict__ w,
                                 const float* __restrict__ bg,
                                 const float* __restrict__ bb,
                                 const float* __restrict__ bm,
                                 const float* __restrict__ bv,
                                 float* __restrict__ out,
                                 int stride, int Ho, int Wo, int total)
{
    int idx = blockIdx.x * blockDim.x + threadIdx.x;
    if (idx >= total) return;
    int xo = idx % Wo;
    int t  = idx / Wo;
    int yo = t % Ho; t /= Ho;
    int c  = t % CH;
    int b  = t / CH;

    const float* xp = x + (size_t)(b * CH + c) * S1;
    const float* wp = w + c * 9;

    int yi0 = yo * stride - 1;
    int xi0 = xo * stride - 1;
    float acc = 0.f;
#pragma unroll
    for (int dy = 0; dy < 3; dy++) {
        int yi = yi0 + dy;
        if (yi < 0 || yi >= HH) continue;
#pragma unroll
        for (int dx = 0; dx < 3; dx++) {
            int xi = xi0 + dx;
            if (xi < 0 || xi >= WW) continue;
            acc += xp[yi * WW + xi] * wp[dy * 3 + dx];
        }
    }
    float inv = bg[c] * rsqrtf(bv[c] + EPS);
    out[idx] = tf32r((acc - bm[c]) * inv + bb[c]);
}

// ---------------------------------------------------------------------------
// tf32 mma wrapper (validated fragment layouts in Round 2)
// ---------------------------------------------------------------------------
__device__ __forceinline__ void mma_tf32(float* c, const unsigned int* a,
                                         const unsigned int* b)
{
    asm volatile(
        "mma.sync.aligned.m16n8k8.row.col.f32.tf32.tf32.f32 "
        "{%0,%1,%2,%3}, {%4,%5,%6,%7}, {%8,%9}, {%0,%1,%2,%3};\n"
        : "+f"(c[0]), "+f"(c[1]), "+f"(c[2]), "+f"(c[3])
        : "r"(a[0]), "r"(a[1]), "r"(a[2]), "r"(a[3]), "r"(b[0]), "r"(b[1]));
}

// ---------------------------------------------------------------------------
// Tensor-core batched GEMM (unchanged from Round 2)
// ---------------------------------------------------------------------------
#define PA 20
#define PB 136

__global__ void __launch_bounds__(256, 2)
gemm_tc_kernel(const float* __restrict__ A,
               const float* __restrict__ Bmat,
               float* __restrict__ C,
               int M, int N, int K,
               const float* __restrict__ bg,
               const float* __restrict__ bb,
               const float* __restrict__ bm,
               const float* __restrict__ bv)
{
    __shared__ __align__(16) float As[2][128 * PA];
    __shared__ __align__(16) float Bs[2][16 * PB];

    const int tid  = threadIdx.x;
    const int lane = tid & 31;
    const int wid  = tid >> 5;
    const int wm   = (wid >> 2) * 64;
    const int wn   = (wid & 3) * 32;
    const int g    = lane >> 2;
    const int t    = lane & 3;

    const int row0  = blockIdx.y * 128;
    const int col0  = blockIdx.x * 128;
    const int batch = blockIdx.z;
    const float* Bb = Bmat + (size_t)batch * K * N;
    float*       Cb = C    + (size_t)batch * M * N;

    const int am0 = tid >> 2;
    const int af4 = (tid & 3) * 4;
    const int bk0 = tid >> 5;
    const int bn  = (tid & 31) * 4;
    const bool bok = (col0 + bn) < N;

    float c[4][4][4];
#pragma unroll
    for (int i = 0; i < 4; i++)
#pragma unroll
        for (int j = 0; j < 4; j++)
#pragma unroll
            for (int l = 0; l < 4; l++) c[i][j][l] = 0.f;

    const int NKT = K / 16;

    {
        float4 ra0 = make_float4(0, 0, 0, 0), ra1 = ra0, rb0 = ra0, rb1 = ra0;
        if (row0 + am0      < M) ra0 = *(const float4*)&A[(size_t)(row0 + am0)      * K + af4];
        if (row0 + am0 + 64 < M) ra1 = *(const float4*)&A[(size_t)(row0 + am0 + 64) * K + af4];
        if (bok) {
            rb0 = *(const float4*)&Bb[(size_t)(bk0    ) * N + col0 + bn];
            rb1 = *(const float4*)&Bb[(size_t)(bk0 + 8) * N + col0 + bn];
        }
        *(float4*)&As[0][(am0)      * PA + af4] = ra0;
        *(float4*)&As[0][(am0 + 64) * PA + af4] = ra1;
        *(float4*)&Bs[0][(bk0)      * PB + bn]  = rb0;
        *(float4*)&Bs[0][(bk0 + 8)  * PB + bn]  = rb1;
    }
    __syncthreads();

    for (int kt = 0; kt < NKT; kt++) {
        const int cur = kt & 1;
        float4 ra0, ra1, rb0, rb1;
        const bool has_next = (kt + 1) < NKT;
        if (has_next) {
            const int k0 = (kt + 1) * 16;
            ra0 = make_float4(0, 0, 0, 0); ra1 = ra0; rb0 = ra0; rb1 = ra0;
            if (row0 + am0      < M) ra0 = *(const float4*)&A[(size_t)(row0 + am0)      * K + k0 + af4];
            if (row0 + am0 + 64 < M) ra1 = *(const float4*)&A[(size_t)(row0 + am0 + 64) * K + k0 + af4];
            if (bok) {
                rb0 = *(const float4*)&Bb[(size_t)(k0 + bk0    ) * N + col0 + bn];
                rb1 = *(const float4*)&Bb[(size_t)(k0 + bk0 + 8) * N + col0 + bn];
            }
        }

        const unsigned int* Asu = (const unsigned int*)&As[cur][0];
        const unsigned int* Bsu = (const unsigned int*)&Bs[cur][0];
#pragma unroll
        for (int ks = 0; ks < 2; ks++) {
            unsigned int af[4][4], bf[4][2];
#pragma unroll
            for (int mt = 0; mt < 4; mt++) {
                int mb = wm + mt * 16;
                af[mt][0] = Asu[(mb + g    ) * PA + ks * 8 + t];
                af[mt][1] = Asu[(mb + g + 8) * PA + ks * 8 + t];
                af[mt][2] = Asu[(mb + g    ) * PA + ks * 8 + t + 4];
                af[mt][3] = Asu[(mb + g + 8) * PA + ks * 8 + t + 4];
            }
#pragma unroll
            for (int nt = 0; nt < 4; nt++) {
                int nb = wn + nt * 8 + g;
                bf[nt][0] = Bsu[(ks * 8 + t    ) * PB + nb];
                bf[nt][1] = Bsu[(ks * 8 + t + 4) * PB + nb];
            }
#pragma unroll
            for (int mt = 0; mt < 4; mt++)
#pragma unroll
                for (int nt = 0; nt < 4; nt++)
                    mma_tf32(c[mt][nt], af[mt], bf[nt]);
        }

        if (has_next) {
            const int nxt = cur ^ 1;
            *(float4*)&As[nxt][(am0)      * PA + af4] = ra0;
            *(float4*)&As[nxt][(am0 + 64) * PA + af4] = ra1;
            *(float4*)&Bs[nxt][(bk0)      * PB + bn]  = rb0;
            *(float4*)&Bs[nxt][(bk0 + 8)  * PB + bn]  = rb1;
        }
        __syncthreads();
    }

#pragma unroll
    for (int mt = 0; mt < 4; mt++) {
        int r0 = row0 + wm + mt * 16 + g;
        int r1 = r0 + 8;
        float sc0 = 1.f, sh0 = 0.f, sc1 = 1.f, sh1 = 0.f;
        if (bg) {
            if (r0 < M) {
                float inv = bg[r0] * rsqrtf(bv[r0] + EPS);
                sc0 = inv; sh0 = bb[r0] - bm[r0] * inv;
            }
            if (r1 < M) {
                float inv = bg[r1] * rsqrtf(bv[r1] + EPS);
                sc1 = inv; sh1 = bb[r1] - bm[r1] * inv;
            }
        }
#pragma unroll
        for (int nt = 0; nt < 4; nt++) {
            int cc = col0 + wn + nt * 8 + 2 * t;
            if (cc < N) {
                if (r0 < M) {
                    float2 v = make_float2(c[mt][nt][0] * sc0 + sh0,
                                           c[mt][nt][1] * sc0 + sh0);
                    *(float2*)&Cb[(size_t)r0 * N + cc] = v;
                }
                if (r1 < M) {
                    float2 v = make_float2(c[mt][nt][2] * sc1 + sh1,
                                           c[mt][nt][3] * sc1 + sh1);
                    *(float2*)&Cb[(size_t)r1 * N + cc] = v;
                }
            }
        }
    }
}

// ---------------------------------------------------------------------------
// Tensor-core attention + residual + per-head LayerNorm + spatial mean.
// One block per (b,h). 8 warps as 4m x 2n grid. Q processed in 64-row tiles.
//   QK: S[64][196] = Q[64][64] * K^T  (B[k=d][n=j] = kv[d][j], no transpose)
//   softmax: 64 row-threads (others stage residual in parallel)
//   PV: O[64][64] = P[64][200] * Vt[200][64] (V transposed at staging)
// ---------------------------------------------------------------------------
__global__ void __launch_bounds__(256, 1)
attn_tc_kernel(const float* __restrict__ qb,
               const float* __restrict__ kvb,
               const float* __restrict__ resb,
               const float* __restrict__ lng,
               const float* __restrict__ lnb,
               float* __restrict__ out)
{
    extern __shared__ float sm[];
    float* Ksm  = sm;                       // [64][KSTR]
    float* Vsm  = Ksm + 64 * KSTR;          // [VROWS][VSTR]
    float* Qsm  = Vsm + VROWS * VSTR;       // [64][QSTR]  (reused as Osm)
    float* Ssm  = Qsm + 64 * QSTR;          // [64][SSTR]
    float* rowZ = Ssm + 64 * SSTR;          // [64]
    float* accs = rowZ + 64;                // [8][64]

    const int bh   = blockIdx.x;
    const int b    = bh >> 3, h = bh & 7;
    const int tid  = threadIdx.x;
    const int wid  = tid >> 5;
    const int lane = tid & 31;
    const int g    = lane >> 2;
    const int t    = lane & 3;
    const int wm   = (wid >> 1) * 16;       // warp m offset (4 m-warps)
    const int wnS  = (wid & 1) * 104;       // warp n offset in S (2 n-warps, 13 mmas)
    const int wnO  = (wid & 1) * 32;        // warp n offset in O (4 mmas)

    const float* kbase = kvb + ((size_t)b * (2 * INNER) + h * DH) * S2;
    const float* vbase = kbase + (size_t)INNER * S2;
    const float* qbase = qb   + ((size_t)b * INNER + h * DH) * S2 * 4;  // S1 = 4*S2
    const float* rbase = resb + (size_t)b * DH * S1;

    // ---- stage K: Ksm[d][j] = tf32(kv[d][j]); pad j in [196,208) with 0
    for (int i = tid; i < 64 * NPAD; i += 256) {
        int d = i / NPAD, j = i - d * NPAD;
        Ksm[d * KSTR + j] = (j < S2) ? tf32r(kbase[(size_t)d * S2 + j]) : 0.f;
    }
    // ---- stage V transposed: Vsm[j][d] = tf32(kv_v[d][j]); pad rows [196,200)=0
    for (int i = tid; i < VROWS * DH; i += 256) {
        int d = i / VROWS, j = i - d * VROWS;
        Vsm[j * VSTR + d] = (j < S2) ? tf32r(vbase[(size_t)d * S2 + j]) : 0.f;
    }
    for (int i = tid; i < 8 * 64; i += 256) accs[i] = 0.f;

    const float lg0 = lng[h * DH + lane], lg1 = lng[h * DH + lane + 32];
    const float lb0 = lnb[h * DH + lane], lb1 = lnb[h * DH + lane + 32];

    const unsigned int* Ksu = (const unsigned int*)Ksm;
    const unsigned int* Vsu = (const unsigned int*)Vsm;
    const unsigned int* Qsu = (const unsigned int*)Qsm;
    const unsigned int* Ssu = (const unsigned int*)Ssm;

    for (int s0 = 0; s0 < S1; s0 += 64) {
        const int len = min(64, S1 - s0);

        __syncthreads();  // prior tile fully consumed (Qsm/Osm, Ssm)

        // ---- stage Q tile transposed: Qsm[r][d] = tf32(q[d][s0+r]); pad rows 0
        for (int i = tid; i < 64 * 64; i += 256) {
            int d = i >> 6, r = i & 63;
            Qsm[r * QSTR + d] = (r < len) ? tf32r(qbase[(size_t)d * S1 + s0 + r]) : 0.f;
        }
        __syncthreads();

        // ---- QK^T: per warp S tile 16 x 104 (13 mmas, 8 k-steps)
        {
            float c[13][4];
#pragma unroll
            for (int nt = 0; nt < 13; nt++)
#pragma unroll
                for (int l = 0; l < 4; l++) c[nt][l] = 0.f;

#pragma unroll
            for (int ks = 0; ks < 8; ks++) {
                unsigned int af[4], bf[13][2];
                af[0] = Qsu[(wm + g    ) * QSTR + ks * 8 + t];
                af[1] = Qsu[(wm + g + 8) * QSTR + ks * 8 + t];
                af[2] = Qsu[(wm + g    ) * QSTR + ks * 8 + t + 4];
                af[3] = Qsu[(wm + g + 8) * QSTR + ks * 8 + t + 4];
#pragma unroll
                for (int nt = 0; nt < 13; nt++) {
                    int nb = wnS + nt * 8 + g;
                    bf[nt][0] = Ksu[(ks * 8 + t    ) * KSTR + nb];
                    bf[nt][1] = Ksu[(ks * 8 + t + 4) * KSTR + nb];
                }
#pragma unroll
                for (int nt = 0; nt < 13; nt++)
                    mma_tf32(c[nt], af, bf[nt]);
            }
            // store scaled S
#pragma unroll
            for (int nt = 0; nt < 13; nt++) {
                int col = wnS + nt * 8 + 2 * t;
                *(float2*)&Ssm[(wm + g    ) * SSTR + col] =
                    make_float2(c[nt][0] * ATT_SCALE, c[nt][1] * ATT_SCALE);
                *(float2*)&Ssm[(wm + g + 8) * SSTR + col] =
                    make_float2(c[nt][2] * ATT_SCALE, c[nt][3] * ATT_SCALE);
            }
        }
        __syncthreads();

        // ---- softmax (tid<64: one row each) || residual staging (tid>=64)
        if (tid < 64) {
            int r = tid;
            if (r < len) {
                float* Srow = &Ssm[r * SSTR];
                float mx = -1e30f;
                for (int j = 0; j < S2; j++) mx = fmaxf(mx, Srow[j]);
                float Z = 0.f;
                for (int j = 0; j < S2; j++) {
                    float e = __expf(Srow[j] - mx);
                    Z += e;
                    Srow[j] = tf32r(e);
                }
#pragma unroll
                for (int j = S2; j < VROWS; j++) Srow[j] = 0.f;
                rowZ[r] = Z;
            }
        } else {
            // Osm (=Qsm) <- residual tile, transposed
            for (int i = tid - 64; i < 64 * 64; i += 192) {
                int d = i >> 6, r = i & 63;
                if (r < len) Qsm[r * QSTR + d] = rbase[(size_t)d * S1 + s0 + r];
            }
        }
        __syncthreads();

        // ---- PV: per warp O tile 16 x 32 (4 mmas, 25 k-steps)
        {
            float o[4][4];
#pragma unroll
            for (int nt = 0; nt < 4; nt++)
#pragma unroll
                for (int l = 0; l < 4; l++) o[nt][l] = 0.f;

            for (int ks = 0; ks < 25; ks++) {
                unsigned int af[4], bf[4][2];
                af[0] = Ssu[(wm + g    ) * SSTR + ks * 8 + t];
                af[1] = Ssu[(wm + g + 8) * SSTR + ks * 8 + t];
                af[2] = Ssu[(wm + g    ) * SSTR + ks * 8 + t + 4];
                af[3] = Ssu[(wm + g + 8) * SSTR + ks * 8 + t + 4];
#pragma unroll
                for (int nt = 0; nt < 4; nt++) {
                    int nb = wnO + nt * 8 + g;
                    bf[nt][0] = Vsu[(ks * 8 + t    ) * VSTR + nb];
                    bf[nt][1] = Vsu[(ks * 8 + t + 4) * VSTR + nb];
                }
#pragma unroll
                for (int nt = 0; nt < 4; nt++)
                    mma_tf32(o[nt], af, bf[nt]);
            }
            // O = o/Z + residual (accumulate into Osm=Qsm)
            int r0 = wm + g, r1 = wm + g + 8;
            float rz0 = 1.f / rowZ[r0];
            float rz1 = 1.f / rowZ[r1];
#pragma unroll
            for (int nt = 0; nt < 4; nt++) {
                int d0 = wnO + nt * 8 + 2 * t;
                Qsm[r0 * QSTR + d0]     += o[nt][0] * rz0;
                Qsm[r0 * QSTR + d0 + 1] += o[nt][1] * rz0;
                Qsm[r1 * QSTR + d0]     += o[nt][2] * rz1;
                Qsm[r1 * QSTR + d0 + 1] += o[nt][3] * rz1;
            }
        }
        __syncthreads();

        // ---- LayerNorm per row + accumulate spatial mean
        for (int r = wid; r < len; r += 8) {
            float x0 = Qsm[r * QSTR + lane];
            float x1 = Qsm[r * QSTR + lane + 32];
            float sum = x0 + x1, sq = x0 * x0 + x1 * x1;
#pragma unroll
            for (int o2 = 16; o2 > 0; o2 >>= 1) {
                sum += __shfl_xor_sync(0xffffffffu, sum, o2);
                sq  += __shfl_xor_sync(0xffffffffu, sq,  o2);
            }
            float mean = sum * (1.f / 64.f);
            float var  = fmaxf(sq * (1.f / 64.f) - mean * mean, 0.f);
            float rs   = 1.f / (sqrtf(var) + EPS);
            accs[wid * 64 + lane]      += (x0 - mean) * rs * lg0 + lb0;
            accs[wid * 64 + lane + 32] += (x1 - mean) * rs * lg1 + lb1;
        }
    }

    __syncthreads();
    if (tid < 64) {
        float s = 0.f;
#pragma unroll
        for (int w2 = 0; w2 < 8; w2++) s += accs[w2 * 64 + tid];
        out[((size_t)b * HEADS + h) * DH + tid] = s * (1.f / 784.f);
    }
}

// ---------------------------------------------------------------------------
extern "C" void kernel_launch(void* const* d_in, const int* in_sizes, int n_in,
                              void* d_out, int out_size)
{
    const float* x      = (const float*)d_in[0];
    const float* w_dwq  = (const float*)d_in[1];
    const float* w_pwq  = (const float*)d_in[2];
    const float* w_dwkv = (const float*)d_in[3];
    const float* w_pwkv = (const float*)d_in[4];
    const float* w_ds   = (const float*)d_in[5];
    const float* ln_g   = (const float*)d_in[6];
    const float* ln_b   = (const float*)d_in[7];
    const float* bnq_g  = (const float*)d_in[8];
    const float* bnq_b  = (const float*)d_in[9];
    const float* bnq_m  = (const float*)d_in[10];
    const float* bnq_v  = (const float*)d_in[11];
    const float* bnkv_g = (const float*)d_in[12];
    const float* bnkv_b = (const float*)d_in[13];
    const float* bnkv_m = (const float*)d_in[14];
    const float* bnkv_v = (const float*)d_in[15];
    const float* bnds_g = (const float*)d_in[16];
    const float* bnds_b = (const float*)d_in[17];
    const float* bnds_m = (const float*)d_in[18];
    const float* bnds_v = (const float*)d_in[19];
    float* out = (float*)d_out;

    void *p_dq, *p_dkv, *p_q, *p_kv, *p_res, *p_xr, *p_wq, *p_wkv, *p_wds;
    cudaGetSymbolAddress(&p_dq,  g_dq);
    cudaGetSymbolAddress(&p_dkv, g_dkv);
    cudaGetSymbolAddress(&p_q,   g_q);
    cudaGetSymbolAddress(&p_kv,  g_kv);
    cudaGetSymbolAddress(&p_res, g_res);
    cudaGetSymbolAddress(&p_xr,  g_xr);
    cudaGetSymbolAddress(&p_wq,  g_wq);
    cudaGetSymbolAddress(&p_wkv, g_wkv);
    cudaGetSymbolAddress(&p_wds, g_wds);

    // 0) tf32 pre-rounding of GEMM operands
    {
        int n4 = NB * CH * S1 / 4;
        round_tf32_kernel<<<(n4 + 255) / 256, 256>>>(x, (float*)p_xr, n4);
    }
    {
        int n4 = INNER * CH / 4;
        round_tf32_kernel<<<(n4 + 255) / 256, 256>>>(w_pwq, (float*)p_wq, n4);
    }
    {
        int n4 = 2 * INNER * CH / 4;
        round_tf32_kernel<<<(n4 + 255) / 256, 256>>>(w_pwkv, (float*)p_wkv, n4);
    }
    {
        int n4 = DH * CH / 4;
        round_tf32_kernel<<<(n4 + 255) / 256, 256>>>(w_ds, (float*)p_wds, n4);
    }

    // 1) depthwise convs + BN
    {
        int total = NB * CH * S1;
        dwconv_bn_kernel<<<(total + 255) / 256, 256>>>(
            x, w_dwq, bnq_g, bnq_b, bnq_m, bnq_v,
            (float*)p_dq, 1, HH, WW, total);
    }
    {
        int total = NB * CH * S2;
        dwconv_bn_kernel<<<(total + 255) / 256, 256>>>(
            x, w_dwkv, bnkv_g, bnkv_b, bnkv_m, bnkv_v,
            (float*)p_dkv, 2, 14, 14, total);
    }

    // 2) pointwise projections (tensor-core GEMMs)
    {
        dim3 grid((S1 + 127) / 128, 1, NB);
        gemm_tc_kernel<<<grid, 256>>>((const float*)p_wds, (const float*)p_xr,
                                      (float*)p_res, DH, S1, CH,
                                      bnds_g, bnds_b, bnds_m, bnds_v);
    }
    {
        dim3 grid((S1 + 127) / 128, INNER / 128, NB);
        gemm_tc_kernel<<<grid, 256>>>((const float*)p_wq, (const float*)p_dq,
                                      (float*)p_q, INNER, S1, CH,
                                      nullptr, nullptr, nullptr, nullptr);
    }
    {
        dim3 grid((S2 + 127) / 128, (2 * INNER) / 128, NB);
        gemm_tc_kernel<<<grid, 256>>>((const float*)p_wkv, (const float*)p_dkv,
                                      (float*)p_kv, 2 * INNER, S2, CH,
                                      nullptr, nullptr, nullptr, nullptr);
    }

    // 3) tensor-core attention + residual + LN + spatial mean
    {
        size_t smem = (size_t)(64 * KSTR + VROWS * VSTR + 64 * QSTR +
                               64 * SSTR + 64 + 8 * 64) * sizeof(float);
        cudaFuncSetAttribute(attn_tc_kernel,
                             cudaFuncAttributeMaxDynamicSharedMemorySize,
                             (int)smem);
        attn_tc_kernel<<<NB * HEADS, 256, smem>>>(
            (const float*)p_q, (const float*)p_kv, (const float*)p_res,
            ln_g, ln_b, out);
    }
}

// round 4
// speedup vs baseline: 2.8625x; 1.0478x over previous
#include <cuda_runtime.h>
#include <math.h>

#define NB     64
#define CH     640
#define HH     28
#define WW     28
#define S1     784
#define S2     196
#define HEADS  8
#define DH     64
#define INNER  512
#define EPS    1e-5f
#define ATT_SCALE 0.125f

// attention tiling constants
#define NPAD   208
#define KSTR   232
#define VROWS  200
#define VSTR   72
#define QSTR   68
#define SSTR   212

// ---- static scratch (no allocations allowed) ----
__device__ float g_dq [NB * CH * S1];
__device__ float g_dkv[NB * CH * S2];
__device__ float g_q  [NB * INNER * S1];
__device__ float g_kv [NB * 2 * INNER * S2];
__device__ float g_res[NB * DH * S1];
__device__ float g_xr [NB * CH * S1];
__device__ float g_wq [INNER * CH];
__device__ float g_wkv[2 * INNER * CH];
__device__ float g_wds[DH * CH];

// ---------------------------------------------------------------------------
__device__ __forceinline__ float tf32r(float x) {
    unsigned int u;
    asm("cvt.rna.tf32.f32 %0, %1;" : "=r"(u) : "f"(x));
    return __uint_as_float(u);
}

__global__ void round_tf32_kernel(const float* __restrict__ in,
                                  float* __restrict__ out, int n4)
{
    int i = blockIdx.x * blockDim.x + threadIdx.x;
    if (i >= n4) return;
    float4 v = ((const float4*)in)[i];
    v.x = tf32r(v.x); v.y = tf32r(v.y); v.z = tf32r(v.z); v.w = tf32r(v.w);
    ((float4*)out)[i] = v;
}

// ---------------------------------------------------------------------------
__global__ void dwconv_bn_kernel(const float* __restrict__ x,
                                 const float* __restrict__ w,
                                 const float* __restrict__ bg,
                                 const float* __restrict__ bb,
                                 const float* __restrict__ bm,
                                 const float* __restrict__ bv,
                                 float* __restrict__ out,
                                 int stride, int Ho, int Wo, int total)
{
    int idx = blockIdx.x * blockDim.x + threadIdx.x;
    if (idx >= total) return;
    int xo = idx % Wo;
    int t  = idx / Wo;
    int yo = t % Ho; t /= Ho;
    int c  = t % CH;
    int b  = t / CH;

    const float* xp = x + (size_t)(b * CH + c) * S1;
    const float* wp = w + c * 9;

    int yi0 = yo * stride - 1;
    int xi0 = xo * stride - 1;
    float acc = 0.f;
#pragma unroll
    for (int dy = 0; dy < 3; dy++) {
        int yi = yi0 + dy;
        if (yi < 0 || yi >= HH) continue;
#pragma unroll
        for (int dx = 0; dx < 3; dx++) {
            int xi = xi0 + dx;
            if (xi < 0 || xi >= WW) continue;
            acc += xp[yi * WW + xi] * wp[dy * 3 + dx];
        }
    }
    float inv = bg[c] * rsqrtf(bv[c] + EPS);
    out[idx] = tf32r((acc - bm[c]) * inv + bb[c]);
}

// ---------------------------------------------------------------------------
__device__ __forceinline__ void mma_tf32(float* c, const unsigned int* a,
                                         const unsigned int* b)
{
    asm volatile(
        "mma.sync.aligned.m16n8k8.row.col.f32.tf32.tf32.f32 "
        "{%0,%1,%2,%3}, {%4,%5,%6,%7}, {%8,%9}, {%0,%1,%2,%3};\n"
        : "+f"(c[0]), "+f"(c[1]), "+f"(c[2]), "+f"(c[3])
        : "r"(a[0]), "r"(a[1]), "r"(a[2]), "r"(a[3]), "r"(b[0]), "r"(b[1]));
}

__device__ __forceinline__ void cp_async16(float* smem_dst, const float* gmem_src,
                                           bool valid)
{
    unsigned int saddr = (unsigned int)__cvta_generic_to_shared(smem_dst);
    int sz = valid ? 16 : 0;
    asm volatile("cp.async.ca.shared.global [%0], [%1], 16, %2;\n"
                 :: "r"(saddr), "l"(gmem_src), "r"(sz));
}
#define CP_COMMIT() asm volatile("cp.async.commit_group;\n" ::: "memory")
#define CP_WAIT2()  asm volatile("cp.async.wait_group 2;\n" ::: "memory")

// ---------------------------------------------------------------------------
// cp.async 4-stage pipelined tf32 tensor-core batched GEMM:
//   C[z][M][N] = A[M][K] * B[z][K][N], A shared across batch.
// Block tile 128x128, 8 warps (warp tile 64x32), k-step 16.
// ---------------------------------------------------------------------------
#define PA 20
#define PB 136
#define STAGES 4
#define ASTG (128 * PA)
#define BSTG (16 * PB)

__global__ void __launch_bounds__(256, 2)
gemm_tc_kernel(const float* __restrict__ A,
               const float* __restrict__ Bmat,
               float* __restrict__ C,
               int M, int N, int K,
               const float* __restrict__ bg,
               const float* __restrict__ bb,
               const float* __restrict__ bm,
               const float* __restrict__ bv)
{
    extern __shared__ __align__(16) float smem[];
    float* As = smem;                   // [STAGES][128*PA]
    float* Bs = smem + STAGES * ASTG;   // [STAGES][16*PB]

    const int tid  = threadIdx.x;
    const int lane = tid & 31;
    const int wid  = tid >> 5;
    const int wm   = (wid >> 2) * 64;
    const int wn   = (wid & 3) * 32;
    const int g    = lane >> 2;
    const int t    = lane & 3;

    const int row0  = blockIdx.y * 128;
    const int col0  = blockIdx.x * 128;
    const int batch = blockIdx.z;
    const float* Bb = Bmat + (size_t)batch * K * N;
    float*       Cb = C    + (size_t)batch * M * N;

    const int am0 = tid >> 2;            // A rows am0 and am0+64
    const int af4 = (tid & 3) * 4;       // k offset within 16
    const int bk0 = tid >> 5;            // B k rows bk0 and bk0+8
    const int bn  = (tid & 31) * 4;      // n offset within 128
    const bool a0ok = (row0 + am0)      < M;
    const bool a1ok = (row0 + am0 + 64) < M;
    const bool bok  = (col0 + bn) < N;

    // clamped source rows (cp.async src must be a valid address even at sz=0)
    const float* a0p = A  + (size_t)(a0ok ? (row0 + am0)      : 0) * K + af4;
    const float* a1p = A  + (size_t)(a1ok ? (row0 + am0 + 64) : 0) * K + af4;
    const float* b0p = Bb + (size_t)bk0       * N + (bok ? (col0 + bn) : 0);
    const float* b1p = Bb + (size_t)(bk0 + 8) * N + (bok ? (col0 + bn) : 0);

    float c[4][4][4];
#pragma unroll
    for (int i = 0; i < 4; i++)
#pragma unroll
        for (int j = 0; j < 4; j++)
#pragma unroll
            for (int l = 0; l < 4; l++) c[i][j][l] = 0.f;

    const int NKT = K / 16;  // 40

#define ISSUE(kt_)                                                          \
    do {                                                                    \
        int s_ = (kt_) & (STAGES - 1);                                      \
        int k0_ = (kt_) * 16;                                               \
        cp_async16(&As[s_ * ASTG + (am0)      * PA + af4], a0p + k0_, a0ok);\
        cp_async16(&As[s_ * ASTG + (am0 + 64) * PA + af4], a1p + k0_, a1ok);\
        cp_async16(&Bs[s_ * BSTG + (bk0)      * PB + bn], b0p + (size_t)k0_ * N, bok); \
        cp_async16(&Bs[s_ * BSTG + (bk0 + 8)  * PB + bn], b1p + (size_t)k0_ * N, bok); \
    } while (0)

    // prologue: 3 stages in flight
#pragma unroll
    for (int kt = 0; kt < STAGES - 1; kt++) {
        ISSUE(kt);
        CP_COMMIT();
    }

    for (int kt = 0; kt < NKT; kt++) {
        CP_WAIT2();          // stage kt landed
        __syncthreads();

        const unsigned int* Asu = (const unsigned int*)&As[(kt & (STAGES - 1)) * ASTG];
        const unsigned int* Bsu = (const unsigned int*)&Bs[(kt & (STAGES - 1)) * BSTG];
#pragma unroll
        for (int ks = 0; ks < 2; ks++) {
            unsigned int af[4][4], bf[4][2];
#pragma unroll
            for (int mt = 0; mt < 4; mt++) {
                int mb = wm + mt * 16;
                af[mt][0] = Asu[(mb + g    ) * PA + ks * 8 + t];
                af[mt][1] = Asu[(mb + g + 8) * PA + ks * 8 + t];
                af[mt][2] = Asu[(mb + g    ) * PA + ks * 8 + t + 4];
                af[mt][3] = Asu[(mb + g + 8) * PA + ks * 8 + t + 4];
            }
#pragma unroll
            for (int nt = 0; nt < 4; nt++) {
                int nb = wn + nt * 8 + g;
                bf[nt][0] = Bsu[(ks * 8 + t    ) * PB + nb];
                bf[nt][1] = Bsu[(ks * 8 + t + 4) * PB + nb];
            }
#pragma unroll
            for (int mt = 0; mt < 4; mt++)
#pragma unroll
                for (int nt = 0; nt < 4; nt++)
                    mma_tf32(c[mt][nt], af[mt], bf[nt]);
        }

        if (kt + STAGES - 1 < NKT) ISSUE(kt + STAGES - 1);
        CP_COMMIT();
    }
#undef ISSUE

    // epilogue
#pragma unroll
    for (int mt = 0; mt < 4; mt++) {
        int r0 = row0 + wm + mt * 16 + g;
        int r1 = r0 + 8;
        float sc0 = 1.f, sh0 = 0.f, sc1 = 1.f, sh1 = 0.f;
        if (bg) {
            if (r0 < M) {
                float inv = bg[r0] * rsqrtf(bv[r0] + EPS);
                sc0 = inv; sh0 = bb[r0] - bm[r0] * inv;
            }
            if (r1 < M) {
                float inv = bg[r1] * rsqrtf(bv[r1] + EPS);
                sc1 = inv; sh1 = bb[r1] - bm[r1] * inv;
            }
        }
#pragma unroll
        for (int nt = 0; nt < 4; nt++) {
            int cc = col0 + wn + nt * 8 + 2 * t;
            if (cc < N) {
                if (r0 < M) {
                    float2 v = make_float2(c[mt][nt][0] * sc0 + sh0,
                                           c[mt][nt][1] * sc0 + sh0);
                    *(float2*)&Cb[(size_t)r0 * N + cc] = v;
                }
                if (r1 < M) {
                    float2 v = make_float2(c[mt][nt][2] * sc1 + sh1,
                                           c[mt][nt][3] * sc1 + sh1);
                    *(float2*)&Cb[(size_t)r1 * N + cc] = v;
                }
            }
        }
    }
}

// ---------------------------------------------------------------------------
// Tensor-core attention + residual + per-head LayerNorm + spatial mean.
// (unchanged from Round 3 — validated)
// ---------------------------------------------------------------------------
__global__ void __launch_bounds__(256, 1)
attn_tc_kernel(const float* __restrict__ qb,
               const float* __restrict__ kvb,
               const float* __restrict__ resb,
               const float* __restrict__ lng,
               const float* __restrict__ lnb,
               float* __restrict__ out)
{
    extern __shared__ float sm[];
    float* Ksm  = sm;
    float* Vsm  = Ksm + 64 * KSTR;
    float* Qsm  = Vsm + VROWS * VSTR;
    float* Ssm  = Qsm + 64 * QSTR;
    float* rowZ = Ssm + 64 * SSTR;
    float* accs = rowZ + 64;

    const int bh   = blockIdx.x;
    const int b    = bh >> 3, h = bh & 7;
    const int tid  = threadIdx.x;
    const int wid  = tid >> 5;
    const int lane = tid & 31;
    const int g    = lane >> 2;
    const int t    = lane & 3;
    const int wm   = (wid >> 1) * 16;
    const int wnS  = (wid & 1) * 104;
    const int wnO  = (wid & 1) * 32;

    const float* kbase = kvb + ((size_t)b * (2 * INNER) + h * DH) * S2;
    const float* vbase = kbase + (size_t)INNER * S2;
    const float* qbase = qb   + ((size_t)b * INNER + h * DH) * S2 * 4;
    const float* rbase = resb + (size_t)b * DH * S1;

    for (int i = tid; i < 64 * NPAD; i += 256) {
        int d = i / NPAD, j = i - d * NPAD;
        Ksm[d * KSTR + j] = (j < S2) ? tf32r(kbase[(size_t)d * S2 + j]) : 0.f;
    }
    for (int i = tid; i < VROWS * DH; i += 256) {
        int d = i / VROWS, j = i - d * VROWS;
        Vsm[j * VSTR + d] = (j < S2) ? tf32r(vbase[(size_t)d * S2 + j]) : 0.f;
    }
    for (int i = tid; i < 8 * 64; i += 256) accs[i] = 0.f;

    const float lg0 = lng[h * DH + lane], lg1 = lng[h * DH + lane + 32];
    const float lb0 = lnb[h * DH + lane], lb1 = lnb[h * DH + lane + 32];

    const unsigned int* Ksu = (const unsigned int*)Ksm;
    const unsigned int* Vsu = (const unsigned int*)Vsm;
    const unsigned int* Qsu = (const unsigned int*)Qsm;
    const unsigned int* Ssu = (const unsigned int*)Ssm;

    for (int s0 = 0; s0 < S1; s0 += 64) {
        const int len = min(64, S1 - s0);

        __syncthreads();

        for (int i = tid; i < 64 * 64; i += 256) {
            int d = i >> 6, r = i & 63;
            Qsm[r * QSTR + d] = (r < len) ? tf32r(qbase[(size_t)d * S1 + s0 + r]) : 0.f;
        }
        __syncthreads();

        {
            float c[13][4];
#pragma unroll
            for (int nt = 0; nt < 13; nt++)
#pragma unroll
                for (int l = 0; l < 4; l++) c[nt][l] = 0.f;

#pragma unroll
            for (int ks = 0; ks < 8; ks++) {
                unsigned int af[4], bf[13][2];
                af[0] = Qsu[(wm + g    ) * QSTR + ks * 8 + t];
                af[1] = Qsu[(wm + g + 8) * QSTR + ks * 8 + t];
                af[2] = Qsu[(wm + g    ) * QSTR + ks * 8 + t + 4];
                af[3] = Qsu[(wm + g + 8) * QSTR + ks * 8 + t + 4];
#pragma unroll
                for (int nt = 0; nt < 13; nt++) {
                    int nb = wnS + nt * 8 + g;
                    bf[nt][0] = Ksu[(ks * 8 + t    ) * KSTR + nb];
                    bf[nt][1] = Ksu[(ks * 8 + t + 4) * KSTR + nb];
                }
#pragma unroll
                for (int nt = 0; nt < 13; nt++)
                    mma_tf32(c[nt], af, bf[nt]);
            }
#pragma unroll
            for (int nt = 0; nt < 13; nt++) {
                int col = wnS + nt * 8 + 2 * t;
                *(float2*)&Ssm[(wm + g    ) * SSTR + col] =
                    make_float2(c[nt][0] * ATT_SCALE, c[nt][1] * ATT_SCALE);
                *(float2*)&Ssm[(wm + g + 8) * SSTR + col] =
                    make_float2(c[nt][2] * ATT_SCALE, c[nt][3] * ATT_SCALE);
            }
        }
        __syncthreads();

        if (tid < 64) {
            int r = tid;
            if (r < len) {
                float* Srow = &Ssm[r * SSTR];
                float mx = -1e30f;
                for (int j = 0; j < S2; j++) mx = fmaxf(mx, Srow[j]);
                float Z = 0.f;
                for (int j = 0; j < S2; j++) {
                    float e = __expf(Srow[j] - mx);
                    Z += e;
                    Srow[j] = tf32r(e);
                }
#pragma unroll
                for (int j = S2; j < VROWS; j++) Srow[j] = 0.f;
                rowZ[r] = Z;
            }
        } else {
            for (int i = tid - 64; i < 64 * 64; i += 192) {
                int d = i >> 6, r = i & 63;
                if (r < len) Qsm[r * QSTR + d] = rbase[(size_t)d * S1 + s0 + r];
            }
        }
        __syncthreads();

        {
            float o[4][4];
#pragma unroll
            for (int nt = 0; nt < 4; nt++)
#pragma unroll
                for (int l = 0; l < 4; l++) o[nt][l] = 0.f;

            for (int ks = 0; ks < 25; ks++) {
                unsigned int af[4], bf[4][2];
                af[0] = Ssu[(wm + g    ) * SSTR + ks * 8 + t];
                af[1] = Ssu[(wm + g + 8) * SSTR + ks * 8 + t];
                af[2] = Ssu[(wm + g    ) * SSTR + ks * 8 + t + 4];
                af[3] = Ssu[(wm + g + 8) * SSTR + ks * 8 + t + 4];
#pragma unroll
                for (int nt = 0; nt < 4; nt++) {
                    int nb = wnO + nt * 8 + g;
                    bf[nt][0] = Vsu[(ks * 8 + t    ) * VSTR + nb];
                    bf[nt][1] = Vsu[(ks * 8 + t + 4) * VSTR + nb];
                }
#pragma unroll
                for (int nt = 0; nt < 4; nt++)
                    mma_tf32(o[nt], af, bf[nt]);
            }
            int r0 = wm + g, r1 = wm + g + 8;
            float rz0 = 1.f / rowZ[r0];
            float rz1 = 1.f / rowZ[r1];
#pragma unroll
            for (int nt = 0; nt < 4; nt++) {
                int d0 = wnO + nt * 8 + 2 * t;
                Qsm[r0 * QSTR + d0]     += o[nt][0] * rz0;
                Qsm[r0 * QSTR + d0 + 1] += o[nt][1] * rz0;
                Qsm[r1 * QSTR + d0]     += o[nt][2] * rz1;
                Qsm[r1 * QSTR + d0 + 1] += o[nt][3] * rz1;
            }
        }
        __syncthreads();

        for (int r = wid; r < len; r += 8) {
            float x0 = Qsm[r * QSTR + lane];
            float x1 = Qsm[r * QSTR + lane + 32];
            float sum = x0 + x1, sq = x0 * x0 + x1 * x1;
#pragma unroll
            for (int o2 = 16; o2 > 0; o2 >>= 1) {
                sum += __shfl_xor_sync(0xffffffffu, sum, o2);
                sq  += __shfl_xor_sync(0xffffffffu, sq,  o2);
            }
            float mean = sum * (1.f / 64.f);
            float var  = fmaxf(sq * (1.f / 64.f) - mean * mean, 0.f);
            float rs   = 1.f / (sqrtf(var) + EPS);
            accs[wid * 64 + lane]      += (x0 - mean) * rs * lg0 + lb0;
            accs[wid * 64 + lane + 32] += (x1 - mean) * rs * lg1 + lb1;
        }
    }

    __syncthreads();
    if (tid < 64) {
        float s = 0.f;
#pragma unroll
        for (int w2 = 0; w2 < 8; w2++) s += accs[w2 * 64 + tid];
        out[((size_t)b * HEADS + h) * DH + tid] = s * (1.f / 784.f);
    }
}

// ---------------------------------------------------------------------------
extern "C" void kernel_launch(void* const* d_in, const int* in_sizes, int n_in,
                              void* d_out, int out_size)
{
    const float* x      = (const float*)d_in[0];
    const float* w_dwq  = (const float*)d_in[1];
    const float* w_pwq  = (const float*)d_in[2];
    const float* w_dwkv = (const float*)d_in[3];
    const float* w_pwkv = (const float*)d_in[4];
    const float* w_ds   = (const float*)d_in[5];
    const float* ln_g   = (const float*)d_in[6];
    const float* ln_b   = (const float*)d_in[7];
    const float* bnq_g  = (const float*)d_in[8];
    const float* bnq_b  = (const float*)d_in[9];
    const float* bnq_m  = (const float*)d_in[10];
    const float* bnq_v  = (const float*)d_in[11];
    const float* bnkv_g = (const float*)d_in[12];
    const float* bnkv_b = (const float*)d_in[13];
    const float* bnkv_m = (const float*)d_in[14];
    const float* bnkv_v = (const float*)d_in[15];
    const float* bnds_g = (const float*)d_in[16];
    const float* bnds_b = (const float*)d_in[17];
    const float* bnds_m = (const float*)d_in[18];
    const float* bnds_v = (const float*)d_in[19];
    float* out = (float*)d_out;

    void *p_dq, *p_dkv, *p_q, *p_kv, *p_res, *p_xr, *p_wq, *p_wkv, *p_wds;
    cudaGetSymbolAddress(&p_dq,  g_dq);
    cudaGetSymbolAddress(&p_dkv, g_dkv);
    cudaGetSymbolAddress(&p_q,   g_q);
    cudaGetSymbolAddress(&p_kv,  g_kv);
    cudaGetSymbolAddress(&p_res, g_res);
    cudaGetSymbolAddress(&p_xr,  g_xr);
    cudaGetSymbolAddress(&p_wq,  g_wq);
    cudaGetSymbolAddress(&p_wkv, g_wkv);
    cudaGetSymbolAddress(&p_wds, g_wds);

    const size_t gemm_smem = (size_t)STAGES * (ASTG + BSTG) * sizeof(float);
    cudaFuncSetAttribute(gemm_tc_kernel,
                         cudaFuncAttributeMaxDynamicSharedMemorySize,
                         (int)gemm_smem);

    // 0) tf32 pre-rounding of GEMM operands
    {
        int n4 = NB * CH * S1 / 4;
        round_tf32_kernel<<<(n4 + 255) / 256, 256>>>(x, (float*)p_xr, n4);
    }
    {
        int n4 = INNER * CH / 4;
        round_tf32_kernel<<<(n4 + 255) / 256, 256>>>(w_pwq, (float*)p_wq, n4);
    }
    {
        int n4 = 2 * INNER * CH / 4;
        round_tf32_kernel<<<(n4 + 255) / 256, 256>>>(w_pwkv, (float*)p_wkv, n4);
    }
    {
        int n4 = DH * CH / 4;
        round_tf32_kernel<<<(n4 + 255) / 256, 256>>>(w_ds, (float*)p_wds, n4);
    }

    // 1) depthwise convs + BN
    {
        int total = NB * CH * S1;
        dwconv_bn_kernel<<<(total + 255) / 256, 256>>>(
            x, w_dwq, bnq_g, bnq_b, bnq_m, bnq_v,
            (float*)p_dq, 1, HH, WW, total);
    }
    {
        int total = NB * CH * S2;
        dwconv_bn_kernel<<<(total + 255) / 256, 256>>>(
            x, w_dwkv, bnkv_g, bnkv_b, bnkv_m, bnkv_v,
            (float*)p_dkv, 2, 14, 14, total);
    }

    // 2) pointwise projections (pipelined tensor-core GEMMs)
    {
        dim3 grid((S1 + 127) / 128, 1, NB);
        gemm_tc_kernel<<<grid, 256, gemm_smem>>>(
            (const float*)p_wds, (const float*)p_xr, (float*)p_res, DH, S1, CH,
            bnds_g, bnds_b, bnds_m, bnds_v);
    }
    {
        dim3 grid((S1 + 127) / 128, INNER / 128, NB);
        gemm_tc_kernel<<<grid, 256, gemm_smem>>>(
            (const float*)p_wq, (const float*)p_dq, (float*)p_q, INNER, S1, CH,
            nullptr, nullptr, nullptr, nullptr);
    }
    {
        dim3 grid((S2 + 127) / 128, (2 * INNER) / 128, NB);
        gemm_tc_kernel<<<grid, 256, gemm_smem>>>(
            (const float*)p_wkv, (const float*)p_dkv, (float*)p_kv, 2 * INNER, S2, CH,
            nullptr, nullptr, nullptr, nullptr);
    }

    // 3) tensor-core attention + residual + LN + spatial mean
    {
        size_t smem = (size_t)(64 * KSTR + VROWS * VSTR + 64 * QSTR +
                               64 * SSTR + 64 + 8 * 64) * sizeof(float);
        cudaFuncSetAttribute(attn_tc_kernel,
                             cudaFuncAttributeMaxDynamicSharedMemorySize,
                             (int)smem);
        attn_tc_kernel<<<NB * HEADS, 256, smem>>>(
            (const float*)p_q, (const float*)p_kv, (const float*)p_res,
            ln_g, ln_b, out);
    }
}

// round 5
// speedup vs baseline: 2.8660x; 1.0012x over previous
#include <cuda_runtime.h>
#include <math.h>

#define NB     64
#define CH     640
#define HH     28
#define WW     28
#define S1     784
#define S2     196
#define HEADS  8
#define DH     64
#define INNER  512
#define EPS    1e-5f
#define ATT_SCALE 0.125f

// attention tiling constants
#define NPAD   208
#define KSTR   232
#define VROWS  200
#define VSTR   72
#define QSTR   68
#define SSTR   212

// ---- static scratch (no allocations allowed) ----
__device__ float g_dq [NB * CH * S1];
__device__ float g_dkv[NB * CH * S2];
__device__ float g_q  [NB * INNER * S1];
__device__ float g_kv [NB * 2 * INNER * S2];
__device__ float g_res[NB * DH * S1];
__device__ float g_xr [NB * CH * S1];
__device__ float g_wq [INNER * CH];
__device__ float g_wkv[2 * INNER * CH];
__device__ float g_wds[DH * CH];

// ---------------------------------------------------------------------------
__device__ __forceinline__ float tf32r(float x) {
    unsigned int u;
    asm("cvt.rna.tf32.f32 %0, %1;" : "=r"(u) : "f"(x));
    return __uint_as_float(u);
}

__global__ void round_tf32_kernel(const float* __restrict__ in,
                                  float* __restrict__ out, int n4)
{
    int i = blockIdx.x * blockDim.x + threadIdx.x;
    if (i >= n4) return;
    float4 v = ((const float4*)in)[i];
    v.x = tf32r(v.x); v.y = tf32r(v.y); v.z = tf32r(v.z); v.w = tf32r(v.w);
    ((float4*)out)[i] = v;
}

// ---------------------------------------------------------------------------
__global__ void dwconv_bn_kernel(const float* __restrict__ x,
                                 const float* __restrict__ w,
                                 const float* __restrict__ bg,
                                 const float* __restrict__ bb,
                                 const float* __restrict__ bm,
                                 const float* __restrict__ bv,
                                 float* __restrict__ out,
                                 int stride, int Ho, int Wo, int total)
{
    int idx = blockIdx.x * blockDim.x + threadIdx.x;
    if (idx >= total) return;
    int xo = idx % Wo;
    int t  = idx / Wo;
    int yo = t % Ho; t /= Ho;
    int c  = t % CH;
    int b  = t / CH;

    const float* xp = x + (size_t)(b * CH + c) * S1;
    const float* wp = w + c * 9;

    int yi0 = yo * stride - 1;
    int xi0 = xo * stride - 1;
    float acc = 0.f;
#pragma unroll
    for (int dy = 0; dy < 3; dy++) {
        int yi = yi0 + dy;
        if (yi < 0 || yi >= HH) continue;
#pragma unroll
        for (int dx = 0; dx < 3; dx++) {
            int xi = xi0 + dx;
            if (xi < 0 || xi >= WW) continue;
            acc += xp[yi * WW + xi] * wp[dy * 3 + dx];
        }
    }
    float inv = bg[c] * rsqrtf(bv[c] + EPS);
    out[idx] = tf32r((acc - bm[c]) * inv + bb[c]);
}

// ---------------------------------------------------------------------------
__device__ __forceinline__ void mma_tf32(float* c, const unsigned int* a,
                                         const unsigned int* b)
{
    asm volatile(
        "mma.sync.aligned.m16n8k8.row.col.f32.tf32.tf32.f32 "
        "{%0,%1,%2,%3}, {%4,%5,%6,%7}, {%8,%9}, {%0,%1,%2,%3};\n"
        : "+f"(c[0]), "+f"(c[1]), "+f"(c[2]), "+f"(c[3])
        : "r"(a[0]), "r"(a[1]), "r"(a[2]), "r"(a[3]), "r"(b[0]), "r"(b[1]));
}

__device__ __forceinline__ void cp_async16(float* smem_dst, const float* gmem_src,
                                           bool valid)
{
    unsigned int saddr = (unsigned int)__cvta_generic_to_shared(smem_dst);
    int sz = valid ? 16 : 0;
    asm volatile("cp.async.ca.shared.global [%0], [%1], 16, %2;\n"
                 :: "r"(saddr), "l"(gmem_src), "r"(sz));
}
#define CP_COMMIT() asm volatile("cp.async.commit_group;\n" ::: "memory")
#define CP_WAIT2()  asm volatile("cp.async.wait_group 2;\n" ::: "memory")

// ---------------------------------------------------------------------------
// cp.async 4-stage pipelined tf32 tensor-core batched GEMM:
//   C[z][M][N] = A[M][K] * B[z][K][N], A shared across batch.
// Block tile 128x128, 8 warps (warp tile 64x32), k-step 16.
// ---------------------------------------------------------------------------
#define PA 20
#define PB 136
#define STAGES 4
#define ASTG (128 * PA)
#define BSTG (16 * PB)

__global__ void __launch_bounds__(256, 2)
gemm_tc_kernel(const float* __restrict__ A,
               const float* __restrict__ Bmat,
               float* __restrict__ C,
               int M, int N, int K,
               const float* __restrict__ bg,
               const float* __restrict__ bb,
               const float* __restrict__ bm,
               const float* __restrict__ bv)
{
    extern __shared__ __align__(16) float smem[];
    float* As = smem;                   // [STAGES][128*PA]
    float* Bs = smem + STAGES * ASTG;   // [STAGES][16*PB]

    const int tid  = threadIdx.x;
    const int lane = tid & 31;
    const int wid  = tid >> 5;
    const int wm   = (wid >> 2) * 64;
    const int wn   = (wid & 3) * 32;
    const int g    = lane >> 2;
    const int t    = lane & 3;

    const int row0  = blockIdx.y * 128;
    const int col0  = blockIdx.x * 128;
    const int batch = blockIdx.z;
    const float* Bb = Bmat + (size_t)batch * K * N;
    float*       Cb = C    + (size_t)batch * M * N;

    const int am0 = tid >> 2;            // A rows am0 and am0+64
    const int af4 = (tid & 3) * 4;       // k offset within 16
    const int bk0 = tid >> 5;            // B k rows bk0 and bk0+8
    const int bn  = (tid & 31) * 4;      // n offset within 128
    const bool a0ok = (row0 + am0)      < M;
    const bool a1ok = (row0 + am0 + 64) < M;
    const bool bok  = (col0 + bn) < N;

    // clamped source rows (cp.async src must be a valid address even at sz=0)
    const float* a0p = A  + (size_t)(a0ok ? (row0 + am0)      : 0) * K + af4;
    const float* a1p = A  + (size_t)(a1ok ? (row0 + am0 + 64) : 0) * K + af4;
    const float* b0p = Bb + (size_t)bk0       * N + (bok ? (col0 + bn) : 0);
    const float* b1p = Bb + (size_t)(bk0 + 8) * N + (bok ? (col0 + bn) : 0);

    float c[4][4][4];
#pragma unroll
    for (int i = 0; i < 4; i++)
#pragma unroll
        for (int j = 0; j < 4; j++)
#pragma unroll
            for (int l = 0; l < 4; l++) c[i][j][l] = 0.f;

    const int NKT = K / 16;  // 40

#define ISSUE(kt_)                                                          \
    do {                                                                    \
        int s_ = (kt_) & (STAGES - 1);                                      \
        int k0_ = (kt_) * 16;                                               \
        cp_async16(&As[s_ * ASTG + (am0)      * PA + af4], a0p + k0_, a0ok);\
        cp_async16(&As[s_ * ASTG + (am0 + 64) * PA + af4], a1p + k0_, a1ok);\
        cp_async16(&Bs[s_ * BSTG + (bk0)      * PB + bn], b0p + (size_t)k0_ * N, bok); \
        cp_async16(&Bs[s_ * BSTG + (bk0 + 8)  * PB + bn], b1p + (size_t)k0_ * N, bok); \
    } while (0)

    // prologue: 3 stages in flight
#pragma unroll
    for (int kt = 0; kt < STAGES - 1; kt++) {
        ISSUE(kt);
        CP_COMMIT();
    }

    for (int kt = 0; kt < NKT; kt++) {
        CP_WAIT2();          // stage kt landed
        __syncthreads();

        const unsigned int* Asu = (const unsigned int*)&As[(kt & (STAGES - 1)) * ASTG];
        const unsigned int* Bsu = (const unsigned int*)&Bs[(kt & (STAGES - 1)) * BSTG];
#pragma unroll
        for (int ks = 0; ks < 2; ks++) {
            unsigned int af[4][4], bf[4][2];
#pragma unroll
            for (int mt = 0; mt < 4; mt++) {
                int mb = wm + mt * 16;
                af[mt][0] = Asu[(mb + g    ) * PA + ks * 8 + t];
                af[mt][1] = Asu[(mb + g + 8) * PA + ks * 8 + t];
                af[mt][2] = Asu[(mb + g    ) * PA + ks * 8 + t + 4];
                af[mt][3] = Asu[(mb + g + 8) * PA + ks * 8 + t + 4];
            }
#pragma unroll
            for (int nt = 0; nt < 4; nt++) {
                int nb = wn + nt * 8 + g;
                bf[nt][0] = Bsu[(ks * 8 + t    ) * PB + nb];
                bf[nt][1] = Bsu[(ks * 8 + t + 4) * PB + nb];
            }
#pragma unroll
            for (int mt = 0; mt < 4; mt++)
#pragma unroll
                for (int nt = 0; nt < 4; nt++)
                    mma_tf32(c[mt][nt], af[mt], bf[nt]);
        }

        if (kt + STAGES - 1 < NKT) ISSUE(kt + STAGES - 1);
        CP_COMMIT();
    }
#undef ISSUE

    // epilogue
#pragma unroll
    for (int mt = 0; mt < 4; mt++) {
        int r0 = row0 + wm + mt * 16 + g;
        int r1 = r0 + 8;
        float sc0 = 1.f, sh0 = 0.f, sc1 = 1.f, sh1 = 0.f;
        if (bg) {
            if (r0 < M) {
                float inv = bg[r0] * rsqrtf(bv[r0] + EPS);
                sc0 = inv; sh0 = bb[r0] - bm[r0] * inv;
            }
            if (r1 < M) {
                float inv = bg[r1] * rsqrtf(bv[r1] + EPS);
                sc1 = inv; sh1 = bb[r1] - bm[r1] * inv;
            }
        }
#pragma unroll
        for (int nt = 0; nt < 4; nt++) {
            int cc = col0 + wn + nt * 8 + 2 * t;
            if (cc < N) {
                if (r0 < M) {
                    float2 v = make_float2(c[mt][nt][0] * sc0 + sh0,
                                           c[mt][nt][1] * sc0 + sh0);
                    *(float2*)&Cb[(size_t)r0 * N + cc] = v;
                }
                if (r1 < M) {
                    float2 v = make_float2(c[mt][nt][2] * sc1 + sh1,
                                           c[mt][nt][3] * sc1 + sh1);
                    *(float2*)&Cb[(size_t)r1 * N + cc] = v;
                }
            }
        }
    }
}

// ---------------------------------------------------------------------------
// Tensor-core attention + residual + per-head LayerNorm + spatial mean.
// (unchanged from Round 3 — validated)
// ---------------------------------------------------------------------------
__global__ void __launch_bounds__(256, 1)
attn_tc_kernel(const float* __restrict__ qb,
               const float* __restrict__ kvb,
               const float* __restrict__ resb,
               const float* __restrict__ lng,
               const float* __restrict__ lnb,
               float* __restrict__ out)
{
    extern __shared__ float sm[];
    float* Ksm  = sm;
    float* Vsm  = Ksm + 64 * KSTR;
    float* Qsm  = Vsm + VROWS * VSTR;
    float* Ssm  = Qsm + 64 * QSTR;
    float* rowZ = Ssm + 64 * SSTR;
    float* accs = rowZ + 64;

    const int bh   = blockIdx.x;
    const int b    = bh >> 3, h = bh & 7;
    const int tid  = threadIdx.x;
    const int wid  = tid >> 5;
    const int lane = tid & 31;
    const int g    = lane >> 2;
    const int t    = lane & 3;
    const int wm   = (wid >> 1) * 16;
    const int wnS  = (wid & 1) * 104;
    const int wnO  = (wid & 1) * 32;

    const float* kbase = kvb + ((size_t)b * (2 * INNER) + h * DH) * S2;
    const float* vbase = kbase + (size_t)INNER * S2;
    const float* qbase = qb   + ((size_t)b * INNER + h * DH) * S2 * 4;
    const float* rbase = resb + (size_t)b * DH * S1;

    for (int i = tid; i < 64 * NPAD; i += 256) {
        int d = i / NPAD, j = i - d * NPAD;
        Ksm[d * KSTR + j] = (j < S2) ? tf32r(kbase[(size_t)d * S2 + j]) : 0.f;
    }
    for (int i = tid; i < VROWS * DH; i += 256) {
        int d = i / VROWS, j = i - d * VROWS;
        Vsm[j * VSTR + d] = (j < S2) ? tf32r(vbase[(size_t)d * S2 + j]) : 0.f;
    }
    for (int i = tid; i < 8 * 64; i += 256) accs[i] = 0.f;

    const float lg0 = lng[h * DH + lane], lg1 = lng[h * DH + lane + 32];
    const float lb0 = lnb[h * DH + lane], lb1 = lnb[h * DH + lane + 32];

    const unsigned int* Ksu = (const unsigned int*)Ksm;
    const unsigned int* Vsu = (const unsigned int*)Vsm;
    const unsigned int* Qsu = (const unsigned int*)Qsm;
    const unsigned int* Ssu = (const unsigned int*)Ssm;

    for (int s0 = 0; s0 < S1; s0 += 64) {
        const int len = min(64, S1 - s0);

        __syncthreads();

        for (int i = tid; i < 64 * 64; i += 256) {
            int d = i >> 6, r = i & 63;
            Qsm[r * QSTR + d] = (r < len) ? tf32r(qbase[(size_t)d * S1 + s0 + r]) : 0.f;
        }
        __syncthreads();

        {
            float c[13][4];
#pragma unroll
            for (int nt = 0; nt < 13; nt++)
#pragma unroll
                for (int l = 0; l < 4; l++) c[nt][l] = 0.f;

#pragma unroll
            for (int ks = 0; ks < 8; ks++) {
                unsigned int af[4], bf[13][2];
                af[0] = Qsu[(wm + g    ) * QSTR + ks * 8 + t];
                af[1] = Qsu[(wm + g + 8) * QSTR + ks * 8 + t];
                af[2] = Qsu[(wm + g    ) * QSTR + ks * 8 + t + 4];
                af[3] = Qsu[(wm + g + 8) * QSTR + ks * 8 + t + 4];
#pragma unroll
                for (int nt = 0; nt < 13; nt++) {
                    int nb = wnS + nt * 8 + g;
                    bf[nt][0] = Ksu[(ks * 8 + t    ) * KSTR + nb];
                    bf[nt][1] = Ksu[(ks * 8 + t + 4) * KSTR + nb];
                }
#pragma unroll
                for (int nt = 0; nt < 13; nt++)
                    mma_tf32(c[nt], af, bf[nt]);
            }
#pragma unroll
            for (int nt = 0; nt < 13; nt++) {
                int col = wnS + nt * 8 + 2 * t;
                *(float2*)&Ssm[(wm + g    ) * SSTR + col] =
                    make_float2(c[nt][0] * ATT_SCALE, c[nt][1] * ATT_SCALE);
                *(float2*)&Ssm[(wm + g + 8) * SSTR + col] =
                    make_float2(c[nt][2] * ATT_SCALE, c[nt][3] * ATT_SCALE);
            }
        }
        __syncthreads();

        if (tid < 64) {
            int r = tid;
            if (r < len) {
                float* Srow = &Ssm[r * SSTR];
                float mx = -1e30f;
                for (int j = 0; j < S2; j++) mx = fmaxf(mx, Srow[j]);
                float Z = 0.f;
                for (int j = 0; j < S2; j++) {
                    float e = __expf(Srow[j] - mx);
                    Z += e;
                    Srow[j] = tf32r(e);
                }
#pragma unroll
                for (int j = S2; j < VROWS; j++) Srow[j] = 0.f;
                rowZ[r] = Z;
            }
        } else {
            for (int i = tid - 64; i < 64 * 64; i += 192) {
                int d = i >> 6, r = i & 63;
                if (r < len) Qsm[r * QSTR + d] = rbase[(size_t)d * S1 + s0 + r];
            }
        }
        __syncthreads();

        {
            float o[4][4];
#pragma unroll
            for (int nt = 0; nt < 4; nt++)
#pragma unroll
                for (int l = 0; l < 4; l++) o[nt][l] = 0.f;

            for (int ks = 0; ks < 25; ks++) {
                unsigned int af[4], bf[4][2];
                af[0] = Ssu[(wm + g    ) * SSTR + ks * 8 + t];
                af[1] = Ssu[(wm + g + 8) * SSTR + ks * 8 + t];
                af[2] = Ssu[(wm + g    ) * SSTR + ks * 8 + t + 4];
                af[3] = Ssu[(wm + g + 8) * SSTR + ks * 8 + t + 4];
#pragma unroll
                for (int nt = 0; nt < 4; nt++) {
                    int nb = wnO + nt * 8 + g;
                    bf[nt][0] = Vsu[(ks * 8 + t    ) * VSTR + nb];
                    bf[nt][1] = Vsu[(ks * 8 + t + 4) * VSTR + nb];
                }
#pragma unroll
                for (int nt = 0; nt < 4; nt++)
                    mma_tf32(o[nt], af, bf[nt]);
            }
            int r0 = wm + g, r1 = wm + g + 8;
            float rz0 = 1.f / rowZ[r0];
            float rz1 = 1.f / rowZ[r1];
#pragma unroll
            for (int nt = 0; nt < 4; nt++) {
                int d0 = wnO + nt * 8 + 2 * t;
                Qsm[r0 * QSTR + d0]     += o[nt][0] * rz0;
                Qsm[r0 * QSTR + d0 + 1] += o[nt][1] * rz0;
                Qsm[r1 * QSTR + d0]     += o[nt][2] * rz1;
                Qsm[r1 * QSTR + d0 + 1] += o[nt][3] * rz1;
            }
        }
        __syncthreads();

        for (int r = wid; r < len; r += 8) {
            float x0 = Qsm[r * QSTR + lane];
            float x1 = Qsm[r * QSTR + lane + 32];
            float sum = x0 + x1, sq = x0 * x0 + x1 * x1;
#pragma unroll
            for (int o2 = 16; o2 > 0; o2 >>= 1) {
                sum += __shfl_xor_sync(0xffffffffu, sum, o2);
                sq  += __shfl_xor_sync(0xffffffffu, sq,  o2);
            }
            float mean = sum * (1.f / 64.f);
            float var  = fmaxf(sq * (1.f / 64.f) - mean * mean, 0.f);
            float rs   = 1.f / (sqrtf(var) + EPS);
            accs[wid * 64 + lane]      += (x0 - mean) * rs * lg0 + lb0;
            accs[wid * 64 + lane + 32] += (x1 - mean) * rs * lg1 + lb1;
        }
    }

    __syncthreads();
    if (tid < 64) {
        float s = 0.f;
#pragma unroll
        for (int w2 = 0; w2 < 8; w2++) s += accs[w2 * 64 + tid];
        out[((size_t)b * HEADS + h) * DH + tid] = s * (1.f / 784.f);
    }
}

// ---------------------------------------------------------------------------
extern "C" void kernel_launch(void* const* d_in, const int* in_sizes, int n_in,
                              void* d_out, int out_size)
{
    const float* x      = (const float*)d_in[0];
    const float* w_dwq  = (const float*)d_in[1];
    const float* w_pwq  = (const float*)d_in[2];
    const float* w_dwkv = (const float*)d_in[3];
    const float* w_pwkv = (const float*)d_in[4];
    const float* w_ds   = (const float*)d_in[5];
    const float* ln_g   = (const float*)d_in[6];
    const float* ln_b   = (const float*)d_in[7];
    const float* bnq_g  = (const float*)d_in[8];
    const float* bnq_b  = (const float*)d_in[9];
    const float* bnq_m  = (const float*)d_in[10];
    const float* bnq_v  = (const float*)d_in[11];
    const float* bnkv_g = (const float*)d_in[12];
    const float* bnkv_b = (const float*)d_in[13];
    const float* bnkv_m = (const float*)d_in[14];
    const float* bnkv_v = (const float*)d_in[15];
    const float* bnds_g = (const float*)d_in[16];
    const float* bnds_b = (const float*)d_in[17];
    const float* bnds_m = (const float*)d_in[18];
    const float* bnds_v = (const float*)d_in[19];
    float* out = (float*)d_out;

    void *p_dq, *p_dkv, *p_q, *p_kv, *p_res, *p_xr, *p_wq, *p_wkv, *p_wds;
    cudaGetSymbolAddress(&p_dq,  g_dq);
    cudaGetSymbolAddress(&p_dkv, g_dkv);
    cudaGetSymbolAddress(&p_q,   g_q);
    cudaGetSymbolAddress(&p_kv,  g_kv);
    cudaGetSymbolAddress(&p_res, g_res);
    cudaGetSymbolAddress(&p_xr,  g_xr);
    cudaGetSymbolAddress(&p_wq,  g_wq);
    cudaGetSymbolAddress(&p_wkv, g_wkv);
    cudaGetSymbolAddress(&p_wds, g_wds);

    const size_t gemm_smem = (size_t)STAGES * (ASTG + BSTG) * sizeof(float);
    cudaFuncSetAttribute(gemm_tc_kernel,
                         cudaFuncAttributeMaxDynamicSharedMemorySize,
                         (int)gemm_smem);

    // 0) tf32 pre-rounding of GEMM operands
    {
        int n4 = NB * CH * S1 / 4;
        round_tf32_kernel<<<(n4 + 255) / 256, 256>>>(x, (float*)p_xr, n4);
    }
    {
        int n4 = INNER * CH / 4;
        round_tf32_kernel<<<(n4 + 255) / 256, 256>>>(w_pwq, (float*)p_wq, n4);
    }
    {
        int n4 = 2 * INNER * CH / 4;
        round_tf32_kernel<<<(n4 + 255) / 256, 256>>>(w_pwkv, (float*)p_wkv, n4);
    }
    {
        int n4 = DH * CH / 4;
        round_tf32_kernel<<<(n4 + 255) / 256, 256>>>(w_ds, (float*)p_wds, n4);
    }

    // 1) depthwise convs + BN
    {
        int total = NB * CH * S1;
        dwconv_bn_kernel<<<(total + 255) / 256, 256>>>(
            x, w_dwq, bnq_g, bnq_b, bnq_m, bnq_v,
            (float*)p_dq, 1, HH, WW, total);
    }
    {
        int total = NB * CH * S2;
        dwconv_bn_kernel<<<(total + 255) / 256, 256>>>(
            x, w_dwkv, bnkv_g, bnkv_b, bnkv_m, bnkv_v,
            (float*)p_dkv, 2, 14, 14, total);
    }

    // 2) pointwise projections (pipelined tensor-core GEMMs)
    {
        dim3 grid((S1 + 127) / 128, 1, NB);
        gemm_tc_kernel<<<grid, 256, gemm_smem>>>(
            (const float*)p_wds, (const float*)p_xr, (float*)p_res, DH, S1, CH,
            bnds_g, bnds_b, bnds_m, bnds_v);
    }
    {
        dim3 grid((S1 + 127) / 128, INNER / 128, NB);
        gemm_tc_kernel<<<grid, 256, gemm_smem>>>(
            (const float*)p_wq, (const float*)p_dq, (float*)p_q, INNER, S1, CH,
            nullptr, nullptr, nullptr, nullptr);
    }
    {
        dim3 grid((S2 + 127) / 128, (2 * INNER) / 128, NB);
        gemm_tc_kernel<<<grid, 256, gemm_smem>>>(
            (const float*)p_wkv, (const float*)p_dkv, (float*)p_kv, 2 * INNER, S2, CH,
            nullptr, nullptr, nullptr, nullptr);
    }

    // 3) tensor-core attention + residual + LN + spatial mean
    {
        size_t smem = (size_t)(64 * KSTR + VROWS * VSTR + 64 * QSTR +
                               64 * SSTR + 64 + 8 * 64) * sizeof(float);
        cudaFuncSetAttribute(attn_tc_kernel,
                             cudaFuncAttributeMaxDynamicSharedMemorySize,
                             (int)smem);
        attn_tc_kernel<<<NB * HEADS, 256, smem>>>(
            (const float*)p_q, (const float*)p_kv, (const float*)p_res,
            ln_g, ln_b, out);
    }
}

// round 8
// speedup vs baseline: 3.4674x; 1.2099x over previous
#include <cuda_runtime.h>
#include <cuda_fp16.h>
#include <math.h>
#include <stdint.h>

#define NB 64
#define CH 640
#define HH 28
#define WW 28
#define S1 784
#define S2 196
#define HEADS 8
#define DH 64
#define INNER 512
#define EPS 1e-5f
#define ATT_SCALE 0.125f
#define KU (CH / 2)          // 320 u32 (half2) along K

// attention tiling constants (validated R3/R4)
#define NPAD 208
#define KSTR 232
#define VROWS 200
#define VSTR 72
#define QSTR 68
#define SSTR 212

// ---- static scratch ----
__device__ uint32_t g_dqh [NB * KU * S1];       // dwconv+BN q,  half2-pairs [b][c/2][s]
__device__ uint32_t g_dkvh[NB * KU * S2];       // dwconv+BN kv
__device__ uint32_t g_xh  [NB * KU * S1];       // x packed
__device__ uint32_t g_wqh [INNER * KU];         // weights packed [m][k/2]
__device__ uint32_t g_wkvh[2 * INNER * KU];
__device__ uint32_t g_wdsh[DH * KU];
__device__ float g_q  [NB * INNER * S1];        // GEMM outputs fp32 [b][co][s]
__device__ float g_kv [NB * 2 * INNER * S2];
__device__ float g_res[NB * DH * S1];

// ---------------------------------------------------------------------------
__device__ __forceinline__ float tf32r(float x) {
    unsigned int u;
    asm("cvt.rna.tf32.f32 %0, %1;" : "=r"(u) : "f"(x));
    return __uint_as_float(u);
}

__device__ __forceinline__ uint32_t h2_u32(float a, float b) {
    __half2 h = __floats2half2_rn(a, b);
    return *reinterpret_cast<uint32_t*>(&h);
}

// pack weights: fp32 [M][K] -> u32 half2 [M][K/2]
__global__ void pack_w_kernel(const float* __restrict__ in,
                              uint32_t* __restrict__ out, int n)
{
    int i = blockIdx.x * blockDim.x + threadIdx.x;
    if (i >= n) return;
    float2 v = ((const float2*)in)[i];
    out[i] = h2_u32(v.x, v.y);
}

// pack x: fp32 [b][C][S1] -> u32 [b][C/2][S1] (channel pairs)
__global__ void pack_x_kernel(const float* __restrict__ x,
                              uint32_t* __restrict__ out, int total)
{
    int i = blockIdx.x * blockDim.x + threadIdx.x;
    if (i >= total) return;
    int s  = i % S1;
    int t  = i / S1;
    int cp = t % KU;
    int b  = t / KU;
    const float* xp = x + ((size_t)b * CH + 2 * cp) * S1 + s;
    out[i] = h2_u32(xp[0], xp[S1]);
}

// ---------------------------------------------------------------------------
// Depthwise 3x3 conv + BN for a channel PAIR; output u32 half2 [b][C/2][S]
// ---------------------------------------------------------------------------
__global__ void dwconv_bn_pack_kernel(const float* __restrict__ x,
                                      const float* __restrict__ w,
                                      const float* __restrict__ bg,
                                      const float* __restrict__ bb,
                                      const float* __restrict__ bm,
                                      const float* __restrict__ bv,
                                      uint32_t* __restrict__ out,
                                      int stride, int Ho, int Wo, int total)
{
    int idx = blockIdx.x * blockDim.x + threadIdx.x;
    if (idx >= total) return;
    int xo = idx % Wo;
    int t  = idx / Wo;
    int yo = t % Ho; t /= Ho;
    int cp = t % KU;
    int b  = t / KU;
    int c0 = 2 * cp;

    const float* xp0 = x + ((size_t)b * CH + c0) * S1;
    const float* xp1 = xp0 + S1;
    const float* wp0 = w + c0 * 9;
    const float* wp1 = wp0 + 9;

    int yi0 = yo * stride - 1, xi0 = xo * stride - 1;
    float a0 = 0.f, a1 = 0.f;
#pragma unroll
    for (int dy = 0; dy < 3; dy++) {
        int yi = yi0 + dy;
        if (yi < 0 || yi >= HH) continue;
#pragma unroll
        for (int dx = 0; dx < 3; dx++) {
            int xi = xi0 + dx;
            if (xi < 0 || xi >= WW) continue;
            float v0 = xp0[yi * WW + xi], v1 = xp1[yi * WW + xi];
            a0 += v0 * wp0[dy * 3 + dx];
            a1 += v1 * wp1[dy * 3 + dx];
        }
    }
    float i0 = bg[c0] * rsqrtf(bv[c0] + EPS);
    float i1 = bg[c0 + 1] * rsqrtf(bv[c0 + 1] + EPS);
    float r0 = (a0 - bm[c0]) * i0 + bb[c0];
    float r1 = (a1 - bm[c0 + 1]) * i1 + bb[c0 + 1];
    out[idx] = h2_u32(r0, r1);
}

// ---------------------------------------------------------------------------
// fp16 mma.sync m16n8k16, fp32 accumulate
// ---------------------------------------------------------------------------
__device__ __forceinline__ void mma_f16(float* c, const unsigned int* a,
                                        const unsigned int* b)
{
    asm volatile(
        "mma.sync.aligned.m16n8k16.row.col.f32.f16.f16.f32 "
        "{%0,%1,%2,%3}, {%4,%5,%6,%7}, {%8,%9}, {%0,%1,%2,%3};\n"
        : "+f"(c[0]), "+f"(c[1]), "+f"(c[2]), "+f"(c[3])
        : "r"(a[0]), "r"(a[1]), "r"(a[2]), "r"(a[3]), "r"(b[0]), "r"(b[1]));
}

__device__ __forceinline__ void cp_async16(uint32_t* smem_dst, const uint32_t* gsrc,
                                           bool valid)
{
    unsigned int saddr = (unsigned int)__cvta_generic_to_shared(smem_dst);
    int sz = valid ? 16 : 0;
    asm volatile("cp.async.ca.shared.global [%0], [%1], 16, %2;\n"
                 :: "r"(saddr), "l"(gsrc), "r"(sz));
}
#define CP_COMMIT() asm volatile("cp.async.commit_group;\n" ::: "memory")
#define CP_WAIT2()  asm volatile("cp.async.wait_group 2;\n" ::: "memory")

// ---------------------------------------------------------------------------
// fp16 cp.async 4-stage pipelined GEMM (u32 = half2 along k):
//   C[z][M][N] = A[M][K] * B[z][K][N]; A u32 [M][KU], B u32 [z][KU][N]
// Block 128x128, 8 warps (64x32), stage = 16 u32 k (=k32), NKT = KU/16 = 20.
// Fragment indexing identical to validated R4 tf32 pattern (u32 units).
// ---------------------------------------------------------------------------
#define PA 20
#define PB 136
#define STAGES 4
#define ASTG (128 * PA)
#define BSTG (16 * PB)

__global__ void __launch_bounds__(256, 2)
gemm_f16_kernel(const uint32_t* __restrict__ A,
                const uint32_t* __restrict__ Bmat,
                float* __restrict__ C,
                int M, int N,
                const float* __restrict__ bg,
                const float* __restrict__ bb,
                const float* __restrict__ bm,
                const float* __restrict__ bv)
{
    extern __shared__ __align__(16) uint32_t smem[];
    uint32_t* As = smem;                 // [STAGES][128*PA]
    uint32_t* Bs = smem + STAGES * ASTG; // [STAGES][16*PB]

    const int tid  = threadIdx.x;
    const int lane = tid & 31;
    const int wid  = tid >> 5;
    const int wm   = (wid >> 2) * 64;
    const int wn   = (wid & 3) * 32;
    const int g    = lane >> 2;
    const int t    = lane & 3;

    const int row0  = blockIdx.y * 128;
    const int col0  = blockIdx.x * 128;
    const int batch = blockIdx.z;
    const uint32_t* Bb = Bmat + (size_t)batch * KU * N;
    float*          Cb = C    + (size_t)batch * M * N;

    // A: 256 threads -> 128 rows x 16 u32 (two 16B cps each)
    const int ar  = tid >> 1;            // row 0..127
    const int ac  = (tid & 1) * 8;       // u32 col 0 or 8
    // B: 16 rows x 128 u32
    const int br  = tid >> 4;            // k-row 0..15
    const int bc  = (tid & 15) * 8;      // u32 col
    const bool aok = (row0 + ar) < M;
    const bool bok = (col0 + bc) < N;

    const uint32_t* ap = A  + (size_t)(aok ? (row0 + ar) : 0) * KU + ac;
    const uint32_t* bp = Bb + (size_t)br * N + (bok ? (col0 + bc) : 0);

    float c[4][4][4];
#pragma unroll
    for (int i = 0; i < 4; i++)
#pragma unroll
        for (int j = 0; j < 4; j++)
#pragma unroll
            for (int l = 0; l < 4; l++) c[i][j][l] = 0.f;

    const int NKT = KU / 16;  // 20

#define ISSUE(kt_)                                                              \
    do {                                                                        \
        int s_ = (kt_) & (STAGES - 1);                                          \
        int k0_ = (kt_) * 16;                                                   \
        cp_async16(&As[s_ * ASTG + ar * PA + ac],     ap + k0_,     aok);       \
        cp_async16(&As[s_ * ASTG + ar * PA + ac + 4], ap + k0_ + 4, aok);       \
        cp_async16(&Bs[s_ * BSTG + br * PB + bc],     bp + (size_t)k0_ * N,     bok); \
        cp_async16(&Bs[s_ * BSTG + br * PB + bc + 4], bp + (size_t)k0_ * N + 4, bok); \
    } while (0)

#pragma unroll
    for (int kt = 0; kt < STAGES - 1; kt++) { ISSUE(kt); CP_COMMIT(); }

    for (int kt = 0; kt < NKT; kt++) {
        CP_WAIT2();
        __syncthreads();

        const uint32_t* Asu = &As[(kt & (STAGES - 1)) * ASTG];
        const uint32_t* Bsu = &Bs[(kt & (STAGES - 1)) * BSTG];
#pragma unroll
        for (int ks = 0; ks < 2; ks++) {
            unsigned int af[4][4], bf[4][2];
#pragma unroll
            for (int mt = 0; mt < 4; mt++) {
                int mb = wm + mt * 16;
                af[mt][0] = Asu[(mb + g    ) * PA + ks * 8 + t];
                af[mt][1] = Asu[(mb + g + 8) * PA + ks * 8 + t];
                af[mt][2] = Asu[(mb + g    ) * PA + ks * 8 + t + 4];
                af[mt][3] = Asu[(mb + g + 8) * PA + ks * 8 + t + 4];
            }
#pragma unroll
            for (int nt = 0; nt < 4; nt++) {
                int nb = wn + nt * 8 + g;
                bf[nt][0] = Bsu[(ks * 8 + t    ) * PB + nb];
                bf[nt][1] = Bsu[(ks * 8 + t + 4) * PB + nb];
            }
#pragma unroll
            for (int mt = 0; mt < 4; mt++)
#pragma unroll
                for (int nt = 0; nt < 4; nt++)
                    mma_f16(c[mt][nt], af[mt], bf[nt]);
        }

        if (kt + STAGES - 1 < NKT) ISSUE(kt + STAGES - 1);
        CP_COMMIT();
    }
#undef ISSUE

#pragma unroll
    for (int mt = 0; mt < 4; mt++) {
        int r0 = row0 + wm + mt * 16 + g;
        int r1 = r0 + 8;
        float sc0 = 1.f, sh0 = 0.f, sc1 = 1.f, sh1 = 0.f;
        if (bg) {
            if (r0 < M) {
                float inv = bg[r0] * rsqrtf(bv[r0] + EPS);
                sc0 = inv; sh0 = bb[r0] - bm[r0] * inv;
            }
            if (r1 < M) {
                float inv = bg[r1] * rsqrtf(bv[r1] + EPS);
                sc1 = inv; sh1 = bb[r1] - bm[r1] * inv;
            }
        }
#pragma unroll
        for (int nt = 0; nt < 4; nt++) {
            int cc = col0 + wn + nt * 8 + 2 * t;
            if (cc < N) {
                if (r0 < M)
                    *(float2*)&Cb[(size_t)r0 * N + cc] =
                        make_float2(c[mt][nt][0] * sc0 + sh0, c[mt][nt][1] * sc0 + sh0);
                if (r1 < M)
                    *(float2*)&Cb[(size_t)r1 * N + cc] =
                        make_float2(c[mt][nt][2] * sc1 + sh1, c[mt][nt][3] * sc1 + sh1);
            }
        }
    }
}

// ---------------------------------------------------------------------------
// tf32 attention + residual + LN + spatial mean (validated R3/R4, unchanged)
// ---------------------------------------------------------------------------
__device__ __forceinline__ void mma_tf32(float* c, const unsigned int* a,
                                         const unsigned int* b)
{
    asm volatile(
        "mma.sync.aligned.m16n8k8.row.col.f32.tf32.tf32.f32 "
        "{%0,%1,%2,%3}, {%4,%5,%6,%7}, {%8,%9}, {%0,%1,%2,%3};\n"
        : "+f"(c[0]), "+f"(c[1]), "+f"(c[2]), "+f"(c[3])
        : "r"(a[0]), "r"(a[1]), "r"(a[2]), "r"(a[3]), "r"(b[0]), "r"(b[1]));
}

__global__ void __launch_bounds__(256, 1)
attn_tc_kernel(const float* __restrict__ qb,
               const float* __restrict__ kvb,
               const float* __restrict__ resb,
               const float* __restrict__ lng,
               const float* __restrict__ lnb,
               float* __restrict__ out)
{
    extern __shared__ float sm[];
    float* Ksm  = sm;
    float* Vsm  = Ksm + 64 * KSTR;
    float* Qsm  = Vsm + VROWS * VSTR;
    float* Ssm  = Qsm + 64 * QSTR;
    float* rowZ = Ssm + 64 * SSTR;
    float* accs = rowZ + 64;

    const int bh   = blockIdx.x;
    const int b    = bh >> 3, h = bh & 7;
    const int tid  = threadIdx.x;
    const int wid  = tid >> 5;
    const int lane = tid & 31;
    const int g    = lane >> 2;
    const int t    = lane & 3;
    const int wm   = (wid >> 1) * 16;
    const int wnS  = (wid & 1) * 104;
    const int wnO  = (wid & 1) * 32;

    const float* kbase = kvb + ((size_t)b * (2 * INNER) + h * DH) * S2;
    const float* vbase = kbase + (size_t)INNER * S2;
    const float* qbase = qb   + ((size_t)b * INNER + h * DH) * S1;
    const float* rbase = resb + (size_t)b * DH * S1;

    for (int i = tid; i < 64 * NPAD; i += 256) {
        int d = i / NPAD, j = i - d * NPAD;
        Ksm[d * KSTR + j] = (j < S2) ? tf32r(kbase[(size_t)d * S2 + j]) : 0.f;
    }
    for (int i = tid; i < VROWS * DH; i += 256) {
        int d = i / VROWS, j = i - d * VROWS;
        Vsm[j * VSTR + d] = (j < S2) ? tf32r(vbase[(size_t)d * S2 + j]) : 0.f;
    }
    for (int i = tid; i < 8 * 64; i += 256) accs[i] = 0.f;

    const float lg0 = lng[h * DH + lane], lg1 = lng[h * DH + lane + 32];
    const float lb0 = lnb[h * DH + lane], lb1 = lnb[h * DH + lane + 32];

    const unsigned int* Ksu = (const unsigned int*)Ksm;
    const unsigned int* Vsu = (const unsigned int*)Vsm;
    const unsigned int* Qsu = (const unsigned int*)Qsm;
    const unsigned int* Ssu = (const unsigned int*)Ssm;

    for (int s0 = 0; s0 < S1; s0 += 64) {
        const int len = min(64, S1 - s0);
        __syncthreads();
        for (int i = tid; i < 64 * 64; i += 256) {
            int d = i >> 6, r = i & 63;
            Qsm[r * QSTR + d] = (r < len) ? tf32r(qbase[(size_t)d * S1 + s0 + r]) : 0.f;
        }
        __syncthreads();

        {
            float c[13][4];
#pragma unroll
            for (int nt = 0; nt < 13; nt++)
#pragma unroll
                for (int l = 0; l < 4; l++) c[nt][l] = 0.f;
#pragma unroll
            for (int ks = 0; ks < 8; ks++) {
                unsigned int af[4], bf[13][2];
                af[0] = Qsu[(wm + g    ) * QSTR + ks * 8 + t];
                af[1] = Qsu[(wm + g + 8) * QSTR + ks * 8 + t];
                af[2] = Qsu[(wm + g    ) * QSTR + ks * 8 + t + 4];
                af[3] = Qsu[(wm + g + 8) * QSTR + ks * 8 + t + 4];
#pragma unroll
                for (int nt = 0; nt < 13; nt++) {
                    int nb = wnS + nt * 8 + g;
                    bf[nt][0] = Ksu[(ks * 8 + t    ) * KSTR + nb];
                    bf[nt][1] = Ksu[(ks * 8 + t + 4) * KSTR + nb];
                }
#pragma unroll
                for (int nt = 0; nt < 13; nt++) mma_tf32(c[nt], af, bf[nt]);
            }
#pragma unroll
            for (int nt = 0; nt < 13; nt++) {
                int col = wnS + nt * 8 + 2 * t;
                *(float2*)&Ssm[(wm + g    ) * SSTR + col] =
                    make_float2(c[nt][0] * ATT_SCALE, c[nt][1] * ATT_SCALE);
                *(float2*)&Ssm[(wm + g + 8) * SSTR + col] =
                    make_float2(c[nt][2] * ATT_SCALE, c[nt][3] * ATT_SCALE);
            }
        }
        __syncthreads();

        if (tid < 64) {
            int r = tid;
            if (r < len) {
                float* Srow = &Ssm[r * SSTR];
                float mx = -1e30f;
                for (int j = 0; j < S2; j++) mx = fmaxf(mx, Srow[j]);
                float Z = 0.f;
                for (int j = 0; j < S2; j++) {
                    float e = __expf(Srow[j] - mx);
                    Z += e;
                    Srow[j] = tf32r(e);
                }
#pragma unroll
                for (int j = S2; j < VROWS; j++) Srow[j] = 0.f;
                rowZ[r] = Z;
            }
        } else {
            for (int i = tid - 64; i < 64 * 64; i += 192) {
                int d = i >> 6, r = i & 63;
                if (r < len) Qsm[r * QSTR + d] = rbase[(size_t)d * S1 + s0 + r];
            }
        }
        __syncthreads();

        {
            float o[4][4];
#pragma unroll
            for (int nt = 0; nt < 4; nt++)
#pragma unroll
                for (int l = 0; l < 4; l++) o[nt][l] = 0.f;
            for (int ks = 0; ks < 25; ks++) {
                unsigned int af[4], bf[4][2];
                af[0] = Ssu[(wm + g    ) * SSTR + ks * 8 + t];
                af[1] = Ssu[(wm + g + 8) * SSTR + ks * 8 + t];
                af[2] = Ssu[(wm + g    ) * SSTR + ks * 8 + t + 4];
                af[3] = Ssu[(wm + g + 8) * SSTR + ks * 8 + t + 4];
#pragma unroll
                for (int nt = 0; nt < 4; nt++) {
                    int nb = wnO + nt * 8 + g;
                    bf[nt][0] = Vsu[(ks * 8 + t    ) * VSTR + nb];
                    bf[nt][1] = Vsu[(ks * 8 + t + 4) * VSTR + nb];
                }
#pragma unroll
                for (int nt = 0; nt < 4; nt++) mma_tf32(o[nt], af, bf[nt]);
            }
            int r0 = wm + g, r1 = wm + g + 8;
            float rz0 = 1.f / rowZ[r0], rz1 = 1.f / rowZ[r1];
#pragma unroll
            for (int nt = 0; nt < 4; nt++) {
                int d0 = wnO + nt * 8 + 2 * t;
                Qsm[r0 * QSTR + d0]     += o[nt][0] * rz0;
                Qsm[r0 * QSTR + d0 + 1] += o[nt][1] * rz0;
                Qsm[r1 * QSTR + d0]     += o[nt][2] * rz1;
                Qsm[r1 * QSTR + d0 + 1] += o[nt][3] * rz1;
            }
        }
        __syncthreads();

        for (int r = wid; r < len; r += 8) {
            float x0 = Qsm[r * QSTR + lane], x1 = Qsm[r * QSTR + lane + 32];
            float sum = x0 + x1, sq = x0 * x0 + x1 * x1;
#pragma unroll
            for (int o2 = 16; o2 > 0; o2 >>= 1) {
                sum += __shfl_xor_sync(0xffffffffu, sum, o2);
                sq  += __shfl_xor_sync(0xffffffffu, sq, o2);
            }
            float mean = sum * (1.f / 64.f);
            float var  = fmaxf(sq * (1.f / 64.f) - mean * mean, 0.f);
            float rs   = 1.f / (sqrtf(var) + EPS);
            accs[wid * 64 + lane]      += (x0 - mean) * rs * lg0 + lb0;
            accs[wid * 64 + lane + 32] += (x1 - mean) * rs * lg1 + lb1;
        }
    }
    __syncthreads();
    if (tid < 64) {
        float s = 0.f;
#pragma unroll
        for (int w2 = 0; w2 < 8; w2++) s += accs[w2 * 64 + tid];
        out[((size_t)b * HEADS + h) * DH + tid] = s * (1.f / 784.f);
    }
}

// ---------------------------------------------------------------------------
extern "C" void kernel_launch(void* const* d_in, const int* in_sizes, int n_in,
                              void* d_out, int out_size)
{
    const float* x      = (const float*)d_in[0];
    const float* w_dwq  = (const float*)d_in[1];
    const float* w_pwq  = (const float*)d_in[2];
    const float* w_dwkv = (const float*)d_in[3];
    const float* w_pwkv = (const float*)d_in[4];
    const float* w_ds   = (const float*)d_in[5];
    const float* ln_g   = (const float*)d_in[6];
    const float* ln_b   = (const float*)d_in[7];
    const float* bnq_g  = (const float*)d_in[8];
    const float* bnq_b  = (const float*)d_in[9];
    const float* bnq_m  = (const float*)d_in[10];
    const float* bnq_v  = (const float*)d_in[11];
    const float* bnkv_g = (const float*)d_in[12];
    const float* bnkv_b = (const float*)d_in[13];
    const float* bnkv_m = (const float*)d_in[14];
    const float* bnkv_v = (const float*)d_in[15];
    const float* bnds_g = (const float*)d_in[16];
    const float* bnds_b = (const float*)d_in[17];
    const float* bnds_m = (const float*)d_in[18];
    const float* bnds_v = (const float*)d_in[19];
    float* out = (float*)d_out;

    void *p_dqh, *p_dkvh, *p_xh, *p_wqh, *p_wkvh, *p_wdsh, *p_q, *p_kv, *p_res;
    cudaGetSymbolAddress(&p_dqh,  g_dqh);
    cudaGetSymbolAddress(&p_dkvh, g_dkvh);
    cudaGetSymbolAddress(&p_xh,   g_xh);
    cudaGetSymbolAddress(&p_wqh,  g_wqh);
    cudaGetSymbolAddress(&p_wkvh, g_wkvh);
    cudaGetSymbolAddress(&p_wdsh, g_wdsh);
    cudaGetSymbolAddress(&p_q,    g_q);
    cudaGetSymbolAddress(&p_kv,   g_kv);
    cudaGetSymbolAddress(&p_res,  g_res);

    const size_t gemm_smem = (size_t)STAGES * (ASTG + BSTG) * sizeof(uint32_t);
    cudaFuncSetAttribute(gemm_f16_kernel,
                         cudaFuncAttributeMaxDynamicSharedMemorySize, (int)gemm_smem);

    // (1) pack q weights
    { int n = INNER * KU; pack_w_kernel<<<(n + 255) / 256, 256>>>(w_pwq, (uint32_t*)p_wqh, n); }
    // (2) dwconv q + BN + pack
    {
        int total = NB * KU * S1;
        dwconv_bn_pack_kernel<<<(total + 255) / 256, 256>>>(
            x, w_dwq, bnq_g, bnq_b, bnq_m, bnq_v, (uint32_t*)p_dqh, 1, HH, WW, total);
    }
    // (3) pack kv weights
    { int n = 2 * INNER * KU; pack_w_kernel<<<(n + 255) / 256, 256>>>(w_pwkv, (uint32_t*)p_wkvh, n); }
    // (4) q GEMM  <-- profiled launch
    {
        dim3 grid((S1 + 127) / 128, INNER / 128, NB);
        gemm_f16_kernel<<<grid, 256, gemm_smem>>>(
            (const uint32_t*)p_wqh, (const uint32_t*)p_dqh, (float*)p_q,
            INNER, S1, nullptr, nullptr, nullptr, nullptr);
    }
    // (5) dwconv kv + BN + pack
    {
        int total = NB * KU * S2;
        dwconv_bn_pack_kernel<<<(total + 255) / 256, 256>>>(
            x, w_dwkv, bnkv_g, bnkv_b, bnkv_m, bnkv_v, (uint32_t*)p_dkvh, 2, 14, 14, total);
    }
    // (6) pack ds weights, (7) pack x
    { int n = DH * KU; pack_w_kernel<<<(n + 255) / 256, 256>>>(w_ds, (uint32_t*)p_wdsh, n); }
    { int total = NB * KU * S1; pack_x_kernel<<<(total + 255) / 256, 256>>>(x, (uint32_t*)p_xh, total); }
    // (8) kv GEMM
    {
        dim3 grid((S2 + 127) / 128, (2 * INNER) / 128, NB);
        gemm_f16_kernel<<<grid, 256, gemm_smem>>>(
            (const uint32_t*)p_wkvh, (const uint32_t*)p_dkvh, (float*)p_kv,
            2 * INNER, S2, nullptr, nullptr, nullptr, nullptr);
    }
    // (9) residual GEMM (+BN)
    {
        dim3 grid((S1 + 127) / 128, 1, NB);
        gemm_f16_kernel<<<grid, 256, gemm_smem>>>(
            (const uint32_t*)p_wdsh, (const uint32_t*)p_xh, (float*)p_res,
            DH, S1, bnds_g, bnds_b, bnds_m, bnds_v);
    }
    // (10) attention + residual + LN + mean
    {
        size_t smem = (size_t)(64 * KSTR + VROWS * VSTR + 64 * QSTR +
                               64 * SSTR + 64 + 8 * 64) * sizeof(float);
        cudaFuncSetAttribute(attn_tc_kernel,
                             cudaFuncAttributeMaxDynamicSharedMemorySize, (int)smem);
        attn_tc_kernel<<<NB * HEADS, 256, smem>>>(
            (const float*)p_q, (const float*)p_kv, (const float*)p_res,
            ln_g, ln_b, out);
    }
}

// round 9
// speedup vs baseline: 4.0799x; 1.1766x over previous
#include <cuda_runtime.h>
#include <cuda_fp16.h>
#include <math.h>
#include <stdint.h>

#define NB 64
#define CH 640
#define HH 28
#define WW 28
#define S1 784
#define S2 196
#define HEADS 8
#define DH 64
#define INNER 512
#define EPS 1e-5f
#define ATT_SCALE 0.125f
#define KU (CH / 2)          // 320 u32 (half2) along K

// fp16 attention tiling (u32 = half2 units; strides conflict-free mod 32)
#define NPAD 208             // padded key count (13 n-tiles of 8... x2 warps)
#define QS2  36              // Qsm row stride (u32), 36%32=4
#define KS2  232             // Ksm row stride (u32), 232%32=8
#define VS2  72              // Vsm row stride (u32), 72%32=8
#define SS   228             // Ssm row stride (fp32/u32), 228%32=4
#define RS   68              // Rsm row stride (fp32)
#define KPJ  104             // padded j-pairs for PV k-dim (13 ksteps x 8)

// ---- static scratch ----
__device__ uint32_t g_dqh [NB * KU * S1];       // dwconv+BN q,  half2-pairs [b][c/2][s]
__device__ uint32_t g_dkvh[NB * KU * S2];       // dwconv+BN kv
__device__ uint32_t g_xh  [NB * KU * S1];       // x packed
__device__ uint32_t g_wqh [INNER * KU];         // weights packed [m][k/2]
__device__ uint32_t g_wkvh[2 * INNER * KU];
__device__ uint32_t g_wdsh[DH * KU];
__device__ float g_q  [NB * INNER * S1];        // GEMM outputs fp32 [b][co][s]
__device__ float g_kv [NB * 2 * INNER * S2];
__device__ float g_res[NB * DH * S1];

// ---------------------------------------------------------------------------
__device__ __forceinline__ uint32_t h2_u32(float a, float b) {
    __half2 h = __floats2half2_rn(a, b);
    return *reinterpret_cast<uint32_t*>(&h);
}

// pack weights: fp32 [M][K] -> u32 half2 [M][K/2]
__global__ void pack_w_kernel(const float* __restrict__ in,
                              uint32_t* __restrict__ out, int n)
{
    int i = blockIdx.x * blockDim.x + threadIdx.x;
    if (i >= n) return;
    float2 v = ((const float2*)in)[i];
    out[i] = h2_u32(v.x, v.y);
}

// pack x: fp32 [b][C][S1] -> u32 [b][C/2][S1] (channel pairs)
__global__ void pack_x_kernel(const float* __restrict__ x,
                              uint32_t* __restrict__ out, int total)
{
    int i = blockIdx.x * blockDim.x + threadIdx.x;
    if (i >= total) return;
    int s  = i % S1;
    int t  = i / S1;
    int cp = t % KU;
    int b  = t / KU;
    const float* xp = x + ((size_t)b * CH + 2 * cp) * S1 + s;
    out[i] = h2_u32(xp[0], xp[S1]);
}

// ---------------------------------------------------------------------------
// Depthwise 3x3 conv + BN for a channel PAIR; output u32 half2 [b][C/2][S]
// ---------------------------------------------------------------------------
__global__ void dwconv_bn_pack_kernel(const float* __restrict__ x,
                                      const float* __restrict__ w,
                                      const float* __restrict__ bg,
                                      const float* __restrict__ bb,
                                      const float* __restrict__ bm,
                                      const float* __restrict__ bv,
                                      uint32_t* __restrict__ out,
                                      int stride, int Ho, int Wo, int total)
{
    int idx = blockIdx.x * blockDim.x + threadIdx.x;
    if (idx >= total) return;
    int xo = idx % Wo;
    int t  = idx / Wo;
    int yo = t % Ho; t /= Ho;
    int cp = t % KU;
    int b  = t / KU;
    int c0 = 2 * cp;

    const float* xp0 = x + ((size_t)b * CH + c0) * S1;
    const float* xp1 = xp0 + S1;
    const float* wp0 = w + c0 * 9;
    const float* wp1 = wp0 + 9;

    int yi0 = yo * stride - 1, xi0 = xo * stride - 1;
    float a0 = 0.f, a1 = 0.f;
#pragma unroll
    for (int dy = 0; dy < 3; dy++) {
        int yi = yi0 + dy;
        if (yi < 0 || yi >= HH) continue;
#pragma unroll
        for (int dx = 0; dx < 3; dx++) {
            int xi = xi0 + dx;
            if (xi < 0 || xi >= WW) continue;
            float v0 = xp0[yi * WW + xi], v1 = xp1[yi * WW + xi];
            a0 += v0 * wp0[dy * 3 + dx];
            a1 += v1 * wp1[dy * 3 + dx];
        }
    }
    float i0 = bg[c0] * rsqrtf(bv[c0] + EPS);
    float i1 = bg[c0 + 1] * rsqrtf(bv[c0 + 1] + EPS);
    float r0 = (a0 - bm[c0]) * i0 + bb[c0];
    float r1 = (a1 - bm[c0 + 1]) * i1 + bb[c0 + 1];
    out[idx] = h2_u32(r0, r1);
}

// ---------------------------------------------------------------------------
// fp16 mma.sync m16n8k16, fp32 accumulate
// ---------------------------------------------------------------------------
__device__ __forceinline__ void mma_f16(float* c, const unsigned int* a,
                                        const unsigned int* b)
{
    asm volatile(
        "mma.sync.aligned.m16n8k16.row.col.f32.f16.f16.f32 "
        "{%0,%1,%2,%3}, {%4,%5,%6,%7}, {%8,%9}, {%0,%1,%2,%3};\n"
        : "+f"(c[0]), "+f"(c[1]), "+f"(c[2]), "+f"(c[3])
        : "r"(a[0]), "r"(a[1]), "r"(a[2]), "r"(a[3]), "r"(b[0]), "r"(b[1]));
}

__device__ __forceinline__ void cp_async16(uint32_t* smem_dst, const uint32_t* gsrc,
                                           bool valid)
{
    unsigned int saddr = (unsigned int)__cvta_generic_to_shared(smem_dst);
    int sz = valid ? 16 : 0;
    asm volatile("cp.async.ca.shared.global [%0], [%1], 16, %2;\n"
                 :: "r"(saddr), "l"(gsrc), "r"(sz));
}
#define CP_COMMIT() asm volatile("cp.async.commit_group;\n" ::: "memory")
#define CP_WAIT2()  asm volatile("cp.async.wait_group 2;\n" ::: "memory")

// ---------------------------------------------------------------------------
// fp16 cp.async 4-stage pipelined GEMM (validated R8, unchanged)
// ---------------------------------------------------------------------------
#define PA 20
#define PB 136
#define STAGES 4
#define ASTG (128 * PA)
#define BSTG (16 * PB)

__global__ void __launch_bounds__(256, 2)
gemm_f16_kernel(const uint32_t* __restrict__ A,
                const uint32_t* __restrict__ Bmat,
                float* __restrict__ C,
                int M, int N,
                const float* __restrict__ bg,
                const float* __restrict__ bb,
                const float* __restrict__ bm,
                const float* __restrict__ bv)
{
    extern __shared__ __align__(16) uint32_t smem[];
    uint32_t* As = smem;                 // [STAGES][128*PA]
    uint32_t* Bs = smem + STAGES * ASTG; // [STAGES][16*PB]

    const int tid  = threadIdx.x;
    const int lane = tid & 31;
    const int wid  = tid >> 5;
    const int wm   = (wid >> 2) * 64;
    const int wn   = (wid & 3) * 32;
    const int g    = lane >> 2;
    const int t    = lane & 3;

    const int row0  = blockIdx.y * 128;
    const int col0  = blockIdx.x * 128;
    const int batch = blockIdx.z;
    const uint32_t* Bb = Bmat + (size_t)batch * KU * N;
    float*          Cb = C    + (size_t)batch * M * N;

    const int ar  = tid >> 1;
    const int ac  = (tid & 1) * 8;
    const int br  = tid >> 4;
    const int bc  = (tid & 15) * 8;
    const bool aok = (row0 + ar) < M;
    const bool bok = (col0 + bc) < N;

    const uint32_t* ap = A  + (size_t)(aok ? (row0 + ar) : 0) * KU + ac;
    const uint32_t* bp = Bb + (size_t)br * N + (bok ? (col0 + bc) : 0);

    float c[4][4][4];
#pragma unroll
    for (int i = 0; i < 4; i++)
#pragma unroll
        for (int j = 0; j < 4; j++)
#pragma unroll
            for (int l = 0; l < 4; l++) c[i][j][l] = 0.f;

    const int NKT = KU / 16;  // 20

#define ISSUE(kt_)                                                              \
    do {                                                                        \
        int s_ = (kt_) & (STAGES - 1);                                          \
        int k0_ = (kt_) * 16;                                                   \
        cp_async16(&As[s_ * ASTG + ar * PA + ac],     ap + k0_,     aok);       \
        cp_async16(&As[s_ * ASTG + ar * PA + ac + 4], ap + k0_ + 4, aok);       \
        cp_async16(&Bs[s_ * BSTG + br * PB + bc],     bp + (size_t)k0_ * N,     bok); \
        cp_async16(&Bs[s_ * BSTG + br * PB + bc + 4], bp + (size_t)k0_ * N + 4, bok); \
    } while (0)

#pragma unroll
    for (int kt = 0; kt < STAGES - 1; kt++) { ISSUE(kt); CP_COMMIT(); }

    for (int kt = 0; kt < NKT; kt++) {
        CP_WAIT2();
        __syncthreads();

        const uint32_t* Asu = &As[(kt & (STAGES - 1)) * ASTG];
        const uint32_t* Bsu = &Bs[(kt & (STAGES - 1)) * BSTG];
#pragma unroll
        for (int ks = 0; ks < 2; ks++) {
            unsigned int af[4][4], bf[4][2];
#pragma unroll
            for (int mt = 0; mt < 4; mt++) {
                int mb = wm + mt * 16;
                af[mt][0] = Asu[(mb + g    ) * PA + ks * 8 + t];
                af[mt][1] = Asu[(mb + g + 8) * PA + ks * 8 + t];
                af[mt][2] = Asu[(mb + g    ) * PA + ks * 8 + t + 4];
                af[mt][3] = Asu[(mb + g + 8) * PA + ks * 8 + t + 4];
            }
#pragma unroll
            for (int nt = 0; nt < 4; nt++) {
                int nb = wn + nt * 8 + g;
                bf[nt][0] = Bsu[(ks * 8 + t    ) * PB + nb];
                bf[nt][1] = Bsu[(ks * 8 + t + 4) * PB + nb];
            }
#pragma unroll
            for (int mt = 0; mt < 4; mt++)
#pragma unroll
                for (int nt = 0; nt < 4; nt++)
                    mma_f16(c[mt][nt], af[mt], bf[nt]);
        }

        if (kt + STAGES - 1 < NKT) ISSUE(kt + STAGES - 1);
        CP_COMMIT();
    }
#undef ISSUE

#pragma unroll
    for (int mt = 0; mt < 4; mt++) {
        int r0 = row0 + wm + mt * 16 + g;
        int r1 = r0 + 8;
        float sc0 = 1.f, sh0 = 0.f, sc1 = 1.f, sh1 = 0.f;
        if (bg) {
            if (r0 < M) {
                float inv = bg[r0] * rsqrtf(bv[r0] + EPS);
                sc0 = inv; sh0 = bb[r0] - bm[r0] * inv;
            }
            if (r1 < M) {
                float inv = bg[r1] * rsqrtf(bv[r1] + EPS);
                sc1 = inv; sh1 = bb[r1] - bm[r1] * inv;
            }
        }
#pragma unroll
        for (int nt = 0; nt < 4; nt++) {
            int cc = col0 + wn + nt * 8 + 2 * t;
            if (cc < N) {
                if (r0 < M)
                    *(float2*)&Cb[(size_t)r0 * N + cc] =
                        make_float2(c[mt][nt][0] * sc0 + sh0, c[mt][nt][1] * sc0 + sh0);
                if (r1 < M)
                    *(float2*)&Cb[(size_t)r1 * N + cc] =
                        make_float2(c[mt][nt][2] * sc1 + sh1, c[mt][nt][3] * sc1 + sh1);
            }
        }
    }
}

// ---------------------------------------------------------------------------
// fp16 tensor-core attention + residual + per-head LayerNorm + spatial mean.
// One block per (b,h), 8 warps (4m x 2n). Per 64-row Q tile:
//   QK: S[64][208] fp16 mma (k=64: 4 ksteps) -> fp32 scores in Ssm
//   softmax (64 row-threads) packs P to half2 IN-PLACE || residual staged
//   PV: O[64][64] fp16 mma (k=208: 13 ksteps), epilogue adds residual to Rsm
//   per-row LN + spatial-mean accumulation
// ---------------------------------------------------------------------------
__global__ void __launch_bounds__(256, 1)
attn_f16_kernel(const float* __restrict__ qb,
                const float* __restrict__ kvb,
                const float* __restrict__ resb,
                const float* __restrict__ lng,
                const float* __restrict__ lnb,
                float* __restrict__ out)
{
    extern __shared__ uint32_t smu[];
    uint32_t* Qsm = smu;                    // [64][QS2]
    uint32_t* Ksm = Qsm + 64 * QS2;         // [32][KS2]
    uint32_t* Vsm = Ksm + 32 * KS2;         // [KPJ][VS2]
    float*    Ssm = (float*)(Vsm + KPJ * VS2);  // [64][SS]
    float*    Rsm = Ssm + 64 * SS;          // [64][RS]
    float*    rowZ = Rsm + 64 * RS;         // [64]
    float*    accs = rowZ + 64;             // [8][64]

    const int bh   = blockIdx.x;
    const int b    = bh >> 3, h = bh & 7;
    const int tid  = threadIdx.x;
    const int wid  = tid >> 5;
    const int lane = tid & 31;
    const int g    = lane >> 2;
    const int t    = lane & 3;
    const int wm   = (wid >> 1) * 16;       // 4 m-warps
    const int wnS  = (wid & 1) * 104;       // QK: 13 n-tiles per warp
    const int wnO  = (wid & 1) * 32;        // PV: 4 n-tiles per warp

    const float* kbase = kvb + ((size_t)b * (2 * INNER) + h * DH) * S2;
    const float* vbase = kbase + (size_t)INNER * S2;
    const float* qbase = qb   + ((size_t)b * INNER + h * DH) * S1;
    const float* rbase = resb + (size_t)b * DH * S1;

    // stage K: Ksm[kp_d][j] = half2(K[j][2kp], K[j][2kp+1]); j>=S2 -> 0
    for (int i = tid; i < 32 * NPAD; i += 256) {
        int kp = i / NPAD, j = i - kp * NPAD;
        float a = 0.f, c = 0.f;
        if (j < S2) {
            a = kbase[(size_t)(2 * kp)     * S2 + j];
            c = kbase[(size_t)(2 * kp + 1) * S2 + j];
        }
        Ksm[kp * KS2 + j] = h2_u32(a, c);
    }
    // stage V: Vsm[kp_j][d] = half2(V[2kp][d], V[2kp+1][d]); kp>=98 -> 0
    for (int i = tid; i < KPJ * DH; i += 256) {
        int kpj = i % KPJ, d = i / KPJ;
        float a = 0.f, c = 0.f;
        if (2 * kpj < S2) {
            const float* vp = vbase + (size_t)d * S2 + 2 * kpj;
            a = vp[0]; c = vp[1];
        }
        Vsm[kpj * VS2 + d] = h2_u32(a, c);
    }
    for (int i = tid; i < 8 * 64; i += 256) accs[i] = 0.f;

    const float lg0 = lng[h * DH + lane], lg1 = lng[h * DH + lane + 32];
    const float lb0 = lnb[h * DH + lane], lb1 = lnb[h * DH + lane + 32];

    for (int s0 = 0; s0 < S1; s0 += 64) {
        const int len = min(64, S1 - s0);
        __syncthreads();   // prior tile fully consumed

        // stage Q: Qsm[r][kp_d]; pad rows -> 0
        for (int i = tid; i < 64 * 32; i += 256) {
            int r = i & 63, kp = i >> 6;
            float a = 0.f, c = 0.f;
            if (r < len) {
                const float* qp = qbase + (size_t)(2 * kp) * S1 + s0 + r;
                a = qp[0]; c = qp[S1];
            }
            Qsm[r * QS2 + kp] = h2_u32(a, c);
        }
        __syncthreads();

        // ---- QK^T (4 ksteps over d=64)
        {
            float c[13][4];
#pragma unroll
            for (int nt = 0; nt < 13; nt++)
#pragma unroll
                for (int l = 0; l < 4; l++) c[nt][l] = 0.f;
#pragma unroll
            for (int ks = 0; ks < 4; ks++) {
                unsigned int af[4], bf[13][2];
                af[0] = Qsm[(wm + g    ) * QS2 + ks * 8 + t];
                af[1] = Qsm[(wm + g + 8) * QS2 + ks * 8 + t];
                af[2] = Qsm[(wm + g    ) * QS2 + ks * 8 + t + 4];
                af[3] = Qsm[(wm + g + 8) * QS2 + ks * 8 + t + 4];
#pragma unroll
                for (int nt = 0; nt < 13; nt++) {
                    int nb = wnS + nt * 8 + g;
                    bf[nt][0] = Ksm[(ks * 8 + t    ) * KS2 + nb];
                    bf[nt][1] = Ksm[(ks * 8 + t + 4) * KS2 + nb];
                }
#pragma unroll
                for (int nt = 0; nt < 13; nt++)
                    mma_f16(c[nt], af, bf[nt]);
            }
#pragma unroll
            for (int nt = 0; nt < 13; nt++) {
                int col = wnS + nt * 8 + 2 * t;
                *(float2*)&Ssm[(wm + g    ) * SS + col] =
                    make_float2(c[nt][0] * ATT_SCALE, c[nt][1] * ATT_SCALE);
                *(float2*)&Ssm[(wm + g + 8) * SS + col] =
                    make_float2(c[nt][2] * ATT_SCALE, c[nt][3] * ATT_SCALE);
            }
        }
        __syncthreads();

        // ---- softmax + in-place half2 pack (tid<64) || residual staging
        if (tid < 64) {
            int r = tid;
            if (r < len) {
                float* Srow = &Ssm[r * SS];
                uint32_t* Prow = (uint32_t*)Srow;
                float mx = -1e30f;
                for (int j = 0; j < S2; j++) mx = fmaxf(mx, Srow[j]);
                float Z = 0.f;
                for (int kp = 0; kp < 98; kp++) {   // 196 = 2*98
                    float e0 = __expf(Srow[2 * kp]     - mx);
                    float e1 = __expf(Srow[2 * kp + 1] - mx);
                    Z += e0 + e1;
                    Prow[kp] = h2_u32(e0, e1);      // word kp <= word 2kp: safe
                }
#pragma unroll
                for (int kp = 98; kp < KPJ; kp++) Prow[kp] = 0u;
                rowZ[r] = Z;
            }
        } else {
            for (int i = tid - 64; i < 64 * 64; i += 192) {
                int d = i >> 6, r = i & 63;
                if (r < len) Rsm[r * RS + d] = rbase[(size_t)d * S1 + s0 + r];
            }
        }
        __syncthreads();

        // ---- PV (13 ksteps over j=208)
        {
            float o[4][4];
#pragma unroll
            for (int nt = 0; nt < 4; nt++)
#pragma unroll
                for (int l = 0; l < 4; l++) o[nt][l] = 0.f;

            const uint32_t* Ssu = (const uint32_t*)Ssm;
#pragma unroll
            for (int ks = 0; ks < 13; ks++) {
                unsigned int af[4], bf[4][2];
                af[0] = Ssu[(wm + g    ) * SS + ks * 8 + t];
                af[1] = Ssu[(wm + g + 8) * SS + ks * 8 + t];
                af[2] = Ssu[(wm + g    ) * SS + ks * 8 + t + 4];
                af[3] = Ssu[(wm + g + 8) * SS + ks * 8 + t + 4];
#pragma unroll
                for (int nt = 0; nt < 4; nt++) {
                    int nb = wnO + nt * 8 + g;
                    bf[nt][0] = Vsm[(ks * 8 + t    ) * VS2 + nb];
                    bf[nt][1] = Vsm[(ks * 8 + t + 4) * VS2 + nb];
                }
#pragma unroll
                for (int nt = 0; nt < 4; nt++)
                    mma_f16(o[nt], af, bf[nt]);
            }
            int r0 = wm + g, r1 = wm + g + 8;
            float rz0 = 1.f / rowZ[r0], rz1 = 1.f / rowZ[r1];
#pragma unroll
            for (int nt = 0; nt < 4; nt++) {
                int d0 = wnO + nt * 8 + 2 * t;
                Rsm[r0 * RS + d0]     += o[nt][0] * rz0;
                Rsm[r0 * RS + d0 + 1] += o[nt][1] * rz0;
                Rsm[r1 * RS + d0]     += o[nt][2] * rz1;
                Rsm[r1 * RS + d0 + 1] += o[nt][3] * rz1;
            }
        }
        __syncthreads();

        // ---- LayerNorm + spatial-mean accumulation
        for (int r = wid; r < len; r += 8) {
            float x0 = Rsm[r * RS + lane], x1 = Rsm[r * RS + lane + 32];
            float sum = x0 + x1, sq = x0 * x0 + x1 * x1;
#pragma unroll
            for (int o2 = 16; o2 > 0; o2 >>= 1) {
                sum += __shfl_xor_sync(0xffffffffu, sum, o2);
                sq  += __shfl_xor_sync(0xffffffffu, sq, o2);
            }
            float mean = sum * (1.f / 64.f);
            float var  = fmaxf(sq * (1.f / 64.f) - mean * mean, 0.f);
            float rs   = 1.f / (sqrtf(var) + EPS);
            accs[wid * 64 + lane]      += (x0 - mean) * rs * lg0 + lb0;
            accs[wid * 64 + lane + 32] += (x1 - mean) * rs * lg1 + lb1;
        }
    }
    __syncthreads();
    if (tid < 64) {
        float s = 0.f;
#pragma unroll
        for (int w2 = 0; w2 < 8; w2++) s += accs[w2 * 64 + tid];
        out[((size_t)b * HEADS + h) * DH + tid] = s * (1.f / 784.f);
    }
}

// ---------------------------------------------------------------------------
extern "C" void kernel_launch(void* const* d_in, const int* in_sizes, int n_in,
                              void* d_out, int out_size)
{
    const float* x      = (const float*)d_in[0];
    const float* w_dwq  = (const float*)d_in[1];
    const float* w_pwq  = (const float*)d_in[2];
    const float* w_dwkv = (const float*)d_in[3];
    const float* w_pwkv = (const float*)d_in[4];
    const float* w_ds   = (const float*)d_in[5];
    const float* ln_g   = (const float*)d_in[6];
    const float* ln_b   = (const float*)d_in[7];
    const float* bnq_g  = (const float*)d_in[8];
    const float* bnq_b  = (const float*)d_in[9];
    const float* bnq_m  = (const float*)d_in[10];
    const float* bnq_v  = (const float*)d_in[11];
    const float* bnkv_g = (const float*)d_in[12];
    const float* bnkv_b = (const float*)d_in[13];
    const float* bnkv_m = (const float*)d_in[14];
    const float* bnkv_v = (const float*)d_in[15];
    const float* bnds_g = (const float*)d_in[16];
    const float* bnds_b = (const float*)d_in[17];
    const float* bnds_m = (const float*)d_in[18];
    const float* bnds_v = (const float*)d_in[19];
    float* out = (float*)d_out;

    void *p_dqh, *p_dkvh, *p_xh, *p_wqh, *p_wkvh, *p_wdsh, *p_q, *p_kv, *p_res;
    cudaGetSymbolAddress(&p_dqh,  g_dqh);
    cudaGetSymbolAddress(&p_dkvh, g_dkvh);
    cudaGetSymbolAddress(&p_xh,   g_xh);
    cudaGetSymbolAddress(&p_wqh,  g_wqh);
    cudaGetSymbolAddress(&p_wkvh, g_wkvh);
    cudaGetSymbolAddress(&p_wdsh, g_wdsh);
    cudaGetSymbolAddress(&p_q,    g_q);
    cudaGetSymbolAddress(&p_kv,   g_kv);
    cudaGetSymbolAddress(&p_res,  g_res);

    const size_t gemm_smem = (size_t)STAGES * (ASTG + BSTG) * sizeof(uint32_t);
    cudaFuncSetAttribute(gemm_f16_kernel,
                         cudaFuncAttributeMaxDynamicSharedMemorySize, (int)gemm_smem);

    // (1) pack q weights
    { int n = INNER * KU; pack_w_kernel<<<(n + 255) / 256, 256>>>(w_pwq, (uint32_t*)p_wqh, n); }
    // (2) dwconv q + BN + pack
    {
        int total = NB * KU * S1;
        dwconv_bn_pack_kernel<<<(total + 255) / 256, 256>>>(
            x, w_dwq, bnq_g, bnq_b, bnq_m, bnq_v, (uint32_t*)p_dqh, 1, HH, WW, total);
    }
    // (3) pack kv weights
    { int n = 2 * INNER * KU; pack_w_kernel<<<(n + 255) / 256, 256>>>(w_pwkv, (uint32_t*)p_wkvh, n); }
    // (4) q GEMM
    {
        dim3 grid((S1 + 127) / 128, INNER / 128, NB);
        gemm_f16_kernel<<<grid, 256, gemm_smem>>>(
            (const uint32_t*)p_wqh, (const uint32_t*)p_dqh, (float*)p_q,
            INNER, S1, nullptr, nullptr, nullptr, nullptr);
    }
    // (5) dwconv kv + BN + pack
    {
        int total = NB * KU * S2;
        dwconv_bn_pack_kernel<<<(total + 255) / 256, 256>>>(
            x, w_dwkv, bnkv_g, bnkv_b, bnkv_m, bnkv_v, (uint32_t*)p_dkvh, 2, 14, 14, total);
    }
    // (6) pack ds weights, (7) pack x
    { int n = DH * KU; pack_w_kernel<<<(n + 255) / 256, 256>>>(w_ds, (uint32_t*)p_wdsh, n); }
    { int total = NB * KU * S1; pack_x_kernel<<<(total + 255) / 256, 256>>>(x, (uint32_t*)p_xh, total); }
    // (8) kv GEMM
    {
        dim3 grid((S2 + 127) / 128, (2 * INNER) / 128, NB);
        gemm_f16_kernel<<<grid, 256, gemm_smem>>>(
            (const uint32_t*)p_wkvh, (const uint32_t*)p_dkvh, (float*)p_kv,
            2 * INNER, S2, nullptr, nullptr, nullptr, nullptr);
    }
    // (9) residual GEMM (+BN)
    {
        dim3 grid((S1 + 127) / 128, 1, NB);
        gemm_f16_kernel<<<grid, 256, gemm_smem>>>(
            (const uint32_t*)p_wdsh, (const uint32_t*)p_xh, (float*)p_res,
            DH, S1, bnds_g, bnds_b, bnds_m, bnds_v);
    }
    // (10) fp16 attention + residual + LN + mean
    {
        size_t smem = (size_t)(64 * QS2 + 32 * KS2 + KPJ * VS2 +
                               64 * SS + 64 * RS + 64 + 8 * 64) * 4;
        cudaFuncSetAttribute(attn_f16_kernel,
                             cudaFuncAttributeMaxDynamicSharedMemorySize, (int)smem);
        attn_f16_kernel<<<NB * HEADS, 256, smem>>>(
            (const float*)p_q, (const float*)p_kv, (const float*)p_res,
            ln_g, ln_b, out);
    }
}